// round 1
// baseline (speedup 1.0000x reference)
#include <cuda_runtime.h>
#include <cmath>

#define Bq 16
#define Cq 256
#define Tq 128
#define Vq 64
#define Kq 8
#define Oq 256
#define TVq 8192            // T*V
#define CNT 131072          // B*T*V  (per-channel BN count)

// ---------------- scratch (device globals: no allocation allowed) ----------------
__device__ float g_tp[Bq*Cq*Vq];        // [b][c][v]   mean over T
__device__ float g_x1[Bq*Oq*Vq];        // [b][o][v]
__device__ float g_x2[Bq*Oq*Vq];
__device__ float g_M [Bq*Kq*Vq*Vq];     // [b][k][v][w]  = A_param + beta*softmax
__device__ float g_bufA[Bq*Oq*TVq];     // stem conv out (y), later head conv out (z)
__device__ float g_bufB[Bq*Oq*TVq];     // stage-5 output (y2)
__device__ float g_stats[4*Oq];         // [0]=sum(y) [1]=sumsq(y) [2]=sum(z) [3]=sumsq(z)

// ---------------- kernels ----------------

__global__ void k_zero() {
    int i = threadIdx.x;
    if (i < 4*Oq) g_stats[i] = 0.f;
}

// tp[b,c,v] = mean_t x[b,c,t,v]
__global__ void k_meanT(const float* __restrict__ x) {
    int bc = blockIdx.x;           // b*C + c
    int v  = threadIdx.x;
    const float* p = x + (size_t)bc * TVq + v;
    float s = 0.f;
    #pragma unroll 8
    for (int t = 0; t < Tq; t++) s += p[t*Vq];
    g_tp[bc*Vq + v] = s * (1.f/Tq);
}

// x1[b,o,v] = sum_c tp[b,c,v]*w1[o,c] + b1[o]   (and x2)
__global__ void k_x1x2(const float* __restrict__ w1, const float* __restrict__ b1,
                       const float* __restrict__ w2, const float* __restrict__ b2) {
    int bo = blockIdx.x;            // b*256 + o
    int b  = bo >> 8, o = bo & 255;
    int v  = threadIdx.x;
    const float* tp = g_tp + (size_t)b*Cq*Vq + v;
    float a1 = 0.f, a2 = 0.f;
    #pragma unroll 4
    for (int c = 0; c < Cq; c++) {
        float t = tp[c*Vq];
        a1 = fmaf(t, __ldg(&w1[o*Cq + c]), a1);
        a2 = fmaf(t, __ldg(&w2[o*Cq + c]), a2);
    }
    g_x1[bo*Vq + v] = a1 + b1[o];
    g_x2[bo*Vq + v] = a2 + b2[o];
}

// M[b,k,v,w] = A_param[k,v,w] + beta * softmax_v( sum_c x1[b,k,c,v]*x2[b,k,c,w] )
__global__ void k_adj(const float* __restrict__ Ap, const float* __restrict__ beta_p) {
    __shared__ float x1s[32][Vq];
    __shared__ float x2s[32][Vq];
    __shared__ float S[Vq][Vq];
    int bk = blockIdx.x;            // b*8 + k
    int b = bk >> 3, k = bk & 7;
    int tid = threadIdx.x;

    for (int i = tid; i < 32*Vq; i += 256) {
        int c = i >> 6, v = i & 63;
        int row = (b*Oq + k*32 + c)*Vq + v;
        x1s[c][v] = g_x1[row];
        x2s[c][v] = g_x2[row];
    }
    __syncthreads();

    for (int i = tid; i < Vq*Vq; i += 256) {
        int v = i >> 6, w = i & 63;
        float s = 0.f;
        #pragma unroll
        for (int c = 0; c < 32; c++) s = fmaf(x1s[c][v], x2s[c][w], s);
        S[v][w] = s;
    }
    __syncthreads();

    if (tid < Vq) {
        int w = tid;
        float m = -1e30f;
        for (int v = 0; v < Vq; v++) m = fmaxf(m, S[v][w]);
        float sum = 0.f;
        for (int v = 0; v < Vq; v++) { float e = __expf(S[v][w] - m); S[v][w] = e; sum += e; }
        float scl = beta_p[0] / sum;
        for (int v = 0; v < Vq; v++) {
            g_M[((bk*Vq + v) << 6) + w] = Ap[((k*Vq + v) << 6) + w] + S[v][w]*scl;
        }
    }
}

// Y[b, m0+m, n0+n] = sum_c W[m, c] * X[b, c, n]     (bias omitted: cancels in BN)
// X is either external x (stem) or g_bufB (head); Y is always g_bufA.
__global__ void __launch_bounds__(256) k_gemm(const float* __restrict__ W,
                                              const float* __restrict__ Xext,
                                              int useB) {
    __shared__ float Ws[128][17];
    __shared__ float Xs[16][64];
    int b  = blockIdx.z;
    int m0 = blockIdx.y * 128;
    int n0 = blockIdx.x * 64;
    int tid = threadIdx.x;
    int tx = tid & 15, ty = tid >> 4;

    const float* Xb = (useB ? (const float*)g_bufB : Xext) + (size_t)b*Cq*TVq;

    float acc[8][4];
    #pragma unroll
    for (int i = 0; i < 8; i++)
        #pragma unroll
        for (int j = 0; j < 4; j++) acc[i][j] = 0.f;

    int lw_k = tid & 15, lw_m = tid >> 4;   // W loader
    int lx_n = tid & 63, lx_k = tid >> 6;   // X loader

    for (int k0 = 0; k0 < Cq; k0 += 16) {
        #pragma unroll
        for (int i = 0; i < 8; i++) {
            int m = lw_m + i*16;
            Ws[m][lw_k] = W[(m0 + m)*Cq + k0 + lw_k];
        }
        #pragma unroll
        for (int i = 0; i < 4; i++) {
            int kk = lx_k + i*4;
            Xs[kk][lx_n] = Xb[(size_t)(k0 + kk)*TVq + n0 + lx_n];
        }
        __syncthreads();
        #pragma unroll
        for (int kk = 0; kk < 16; kk++) {
            float4 xv = *(const float4*)&Xs[kk][tx*4];
            float wv[8];
            #pragma unroll
            for (int i = 0; i < 8; i++) wv[i] = Ws[ty*8 + i][kk];
            #pragma unroll
            for (int i = 0; i < 8; i++) {
                acc[i][0] = fmaf(wv[i], xv.x, acc[i][0]);
                acc[i][1] = fmaf(wv[i], xv.y, acc[i][1]);
                acc[i][2] = fmaf(wv[i], xv.z, acc[i][2]);
                acc[i][3] = fmaf(wv[i], xv.w, acc[i][3]);
            }
        }
        __syncthreads();
    }

    float* Yb = g_bufA + (size_t)b*Oq*TVq;
    #pragma unroll
    for (int i = 0; i < 8; i++) {
        *(float4*)&Yb[(size_t)(m0 + ty*8 + i)*TVq + n0 + tx*4] =
            make_float4(acc[i][0], acc[i][1], acc[i][2], acc[i][3]);
    }
}

// per-channel sum & sumsq of g_bufA into g_stats[slot], g_stats[slot+1]
__global__ void k_stats(int slot) {
    int o = blockIdx.x, b = blockIdx.y, tid = threadIdx.x;
    const float* p = g_bufA + (size_t)(b*Oq + o)*TVq;
    float s = 0.f, q = 0.f;
    for (int i = tid; i < TVq; i += 256) { float y = p[i]; s += y; q = fmaf(y, y, q); }
    __shared__ float ss[256], qq[256];
    ss[tid] = s; qq[tid] = q;
    __syncthreads();
    for (int st = 128; st > 0; st >>= 1) {
        if (tid < st) { ss[tid] += ss[tid + st]; qq[tid] += qq[tid + st]; }
        __syncthreads();
    }
    if (tid == 0) {
        atomicAdd(&g_stats[slot*Oq + o],       ss[0]);
        atomicAdd(&g_stats[(slot+1)*Oq + o],   qq[0]);
    }
}

// h = relu(BN(bufA));  A = M + alpha*tanh(x1[v]-x2[w]);  bufB[t,w] = sum_v h[t,v]*A[v,w]
__global__ void __launch_bounds__(256) k_stage5(const float* __restrict__ alpha_p,
                                                const float* __restrict__ gamma,
                                                const float* __restrict__ beta) {
    __shared__ float hs[128][64];
    __shared__ float As[64][64];
    int bx = blockIdx.x;            // b*256 + o,  o = k*32 + c
    int b = bx >> 8, o = bx & 255, k = o >> 5;
    int tid = threadIdx.x;

    float mean = g_stats[o]        * (1.f/CNT);
    float var  = g_stats[Oq + o]   * (1.f/CNT) - mean*mean;
    float scale = gamma[o] * rsqrtf(var + 1e-5f);
    float shift = beta[o] - mean*scale;

    const float* src = g_bufA + (size_t)bx*TVq;
    for (int i = tid; i < TVq; i += 256) {
        float y = fmaf(src[i], scale, shift);
        hs[i >> 6][i & 63] = fmaxf(y, 0.f);
    }

    float alpha = alpha_p[0];
    const float* x1r = g_x1 + bx*Vq;
    const float* x2r = g_x2 + bx*Vq;
    const float* Mp  = g_M + (size_t)(b*Kq + k)*Vq*Vq;
    for (int i = tid; i < Vq*Vq; i += 256) {
        int v = i >> 6, w = i & 63;
        As[v][w] = Mp[i] + alpha * tanhf(x1r[v] - x2r[w]);
    }
    __syncthreads();

    int tx = tid & 15, ty = tid >> 4;
    float acc[8][4];
    #pragma unroll
    for (int i = 0; i < 8; i++)
        #pragma unroll
        for (int j = 0; j < 4; j++) acc[i][j] = 0.f;

    #pragma unroll 8
    for (int v = 0; v < Vq; v++) {
        float4 a4 = *(const float4*)&As[v][tx*4];
        #pragma unroll
        for (int i = 0; i < 8; i++) {
            float h = hs[ty*8 + i][v];
            acc[i][0] = fmaf(h, a4.x, acc[i][0]);
            acc[i][1] = fmaf(h, a4.y, acc[i][1]);
            acc[i][2] = fmaf(h, a4.z, acc[i][2]);
            acc[i][3] = fmaf(h, a4.w, acc[i][3]);
        }
    }

    float* dst = g_bufB + (size_t)bx*TVq;
    #pragma unroll
    for (int i = 0; i < 8; i++) {
        *(float4*)&dst[(ty*8 + i)*Vq + tx*4] =
            make_float4(acc[i][0], acc[i][1], acc[i][2], acc[i][3]);
    }
}

// out = relu(BN(bufA) + x)
__global__ void k_out(const float* __restrict__ x,
                      const float* __restrict__ gamma, const float* __restrict__ beta,
                      float* __restrict__ out) {
    size_t idx = (size_t)blockIdx.x * 256 + threadIdx.x;   // float4 index
    int o = (int)((idx >> 11) & 255);                       // (idx*4 / 8192) % 256
    float mean = g_stats[2*Oq + o] * (1.f/CNT);
    float var  = g_stats[3*Oq + o] * (1.f/CNT) - mean*mean;
    float scale = gamma[o] * rsqrtf(var + 1e-5f);
    float shift = beta[o] - mean*scale;
    float4 z  = ((const float4*)g_bufA)[idx];
    float4 xv = ((const float4*)x)[idx];
    float4 r;
    r.x = fmaxf(fmaf(z.x, scale, shift) + xv.x, 0.f);
    r.y = fmaxf(fmaf(z.y, scale, shift) + xv.y, 0.f);
    r.z = fmaxf(fmaf(z.z, scale, shift) + xv.z, 0.f);
    r.w = fmaxf(fmaf(z.w, scale, shift) + xv.w, 0.f);
    ((float4*)out)[idx] = r;
}

// ---------------- launch ----------------
extern "C" void kernel_launch(void* const* d_in, const int* in_sizes, int n_in,
                              void* d_out, int out_size) {
    const float* x       = (const float*)d_in[0];
    const float* A_param = (const float*)d_in[1];
    const float* alpha   = (const float*)d_in[2];
    const float* beta    = (const float*)d_in[3];
    const float* w1      = (const float*)d_in[4];
    const float* b1      = (const float*)d_in[5];
    const float* w2      = (const float*)d_in[6];
    const float* b2      = (const float*)d_in[7];
    const float* stem_w  = (const float*)d_in[8];
    const float* stem_g  = (const float*)d_in[10];
    const float* stem_be = (const float*)d_in[11];
    const float* head_w  = (const float*)d_in[12];
    const float* head_g  = (const float*)d_in[14];
    const float* head_be = (const float*)d_in[15];
    float* out = (float*)d_out;

    k_zero<<<1, 1024>>>();
    k_meanT<<<Bq*Cq, Vq>>>(x);
    k_x1x2<<<Bq*Oq, Vq>>>(w1, b1, w2, b2);
    k_adj<<<Bq*Kq, 256>>>(A_param, beta);

    // stem conv (bias cancels in BN)
    k_gemm<<<dim3(TVq/64, Oq/128, Bq), 256>>>(stem_w, x, 0);
    k_stats<<<dim3(Oq, Bq), 256>>>(0);

    // BN+relu fused into graph matmul
    k_stage5<<<Bq*Oq, 256>>>(alpha, stem_g, stem_be);

    // head conv
    k_gemm<<<dim3(TVq/64, Oq/128, Bq), 256>>>(head_w, (const float*)0, 1);
    k_stats<<<dim3(Oq, Bq), 256>>>(2);

    k_out<<<(Bq*Oq*TVq/4)/256, 256>>>(x, head_g, head_be, out);
}

// round 2
// speedup vs baseline: 2.3877x; 2.3877x over previous
#include <cuda_runtime.h>
#include <cmath>
#include <cstdint>

#define Bq 16
#define Cq 256
#define Tq 128
#define Vq 64
#define Kq 8
#define Oq 256
#define TVq 8192            // T*V
#define CNT 131072          // B*T*V  (per-channel BN count)

// ---------------- scratch (device globals: no allocation allowed) ----------------
__device__ float g_tp[Bq*Cq*Vq];        // [b][c][v]   mean over T
__device__ float g_x1[Bq*Oq*Vq];        // [b][o][v]
__device__ float g_x2[Bq*Oq*Vq];
__device__ float g_M [Bq*Kq*Vq*Vq];     // [b][k][v][w]  = A_param + beta*softmax
__device__ float g_bufA[Bq*Oq*TVq];     // stem conv out (y), later head conv out (z)
__device__ float g_bufB[Bq*Oq*TVq];     // stage-5 output (y2)
__device__ float g_stats[4*Oq];

// ---------------- helpers ----------------
__device__ __forceinline__ void mma_tf32(float c[4],
                                         uint32_t a0, uint32_t a1, uint32_t a2, uint32_t a3,
                                         uint32_t b0, uint32_t b1) {
    asm volatile(
        "mma.sync.aligned.m16n8k8.row.col.f32.tf32.tf32.f32 "
        "{%0,%1,%2,%3},{%4,%5,%6,%7},{%8,%9},{%0,%1,%2,%3};\n"
        : "+f"(c[0]), "+f"(c[1]), "+f"(c[2]), "+f"(c[3])
        : "r"(a0), "r"(a1), "r"(a2), "r"(a3), "r"(b0), "r"(b1));
}

__device__ __forceinline__ void cpasync16(uint32_t saddr, const void* g) {
    asm volatile("cp.async.cg.shared.global [%0], [%1], 16;\n" :: "r"(saddr), "l"(g));
}
#define CP_COMMIT() asm volatile("cp.async.commit_group;\n" ::: "memory")
#define CP_WAIT0()  asm volatile("cp.async.wait_group 0;\n" ::: "memory")

__device__ __forceinline__ uint32_t fbits(float f) { return __float_as_uint(f); }

// ---------------- small kernels (unchanged) ----------------

__global__ void k_zero() {
    int i = threadIdx.x;
    if (i < 4*Oq) g_stats[i] = 0.f;
}

__global__ void k_meanT(const float* __restrict__ x) {
    int bc = blockIdx.x;
    int v  = threadIdx.x;
    const float* p = x + (size_t)bc * TVq + v;
    float s = 0.f;
    #pragma unroll 8
    for (int t = 0; t < Tq; t++) s += p[t*Vq];
    g_tp[bc*Vq + v] = s * (1.f/Tq);
}

__global__ void k_x1x2(const float* __restrict__ w1, const float* __restrict__ b1,
                       const float* __restrict__ w2, const float* __restrict__ b2) {
    int bo = blockIdx.x;
    int b  = bo >> 8, o = bo & 255;
    int v  = threadIdx.x;
    const float* tp = g_tp + (size_t)b*Cq*Vq + v;
    float a1 = 0.f, a2 = 0.f;
    #pragma unroll 4
    for (int c = 0; c < Cq; c++) {
        float t = tp[c*Vq];
        a1 = fmaf(t, __ldg(&w1[o*Cq + c]), a1);
        a2 = fmaf(t, __ldg(&w2[o*Cq + c]), a2);
    }
    g_x1[bo*Vq + v] = a1 + b1[o];
    g_x2[bo*Vq + v] = a2 + b2[o];
}

__global__ void k_adj(const float* __restrict__ Ap, const float* __restrict__ beta_p) {
    __shared__ float x1s[32][Vq];
    __shared__ float x2s[32][Vq];
    __shared__ float S[Vq][Vq];
    int bk = blockIdx.x;
    int b = bk >> 3, k = bk & 7;
    int tid = threadIdx.x;

    for (int i = tid; i < 32*Vq; i += 256) {
        int c = i >> 6, v = i & 63;
        int row = (b*Oq + k*32 + c)*Vq + v;
        x1s[c][v] = g_x1[row];
        x2s[c][v] = g_x2[row];
    }
    __syncthreads();

    for (int i = tid; i < Vq*Vq; i += 256) {
        int v = i >> 6, w = i & 63;
        float s = 0.f;
        #pragma unroll
        for (int c = 0; c < 32; c++) s = fmaf(x1s[c][v], x2s[c][w], s);
        S[v][w] = s;
    }
    __syncthreads();

    if (tid < Vq) {
        int w = tid;
        float m = -1e30f;
        for (int v = 0; v < Vq; v++) m = fmaxf(m, S[v][w]);
        float sum = 0.f;
        for (int v = 0; v < Vq; v++) { float e = __expf(S[v][w] - m); S[v][w] = e; sum += e; }
        float scl = beta_p[0] / sum;
        for (int v = 0; v < Vq; v++) {
            g_M[((bk*Vq + v) << 6) + w] = Ap[((k*Vq + v) << 6) + w] + S[v][w]*scl;
        }
    }
}

// ---------------- TF32 tensor-core GEMM ----------------
// Y[b, m0+m, n0+n] = sum_c W[m, c] * X[b, c, n]    (bias cancels in BN)
// block tile 128(m) x 128(n), k-step 32, 8 warps in 2(m) x 4(n), warp tile 64x32.
#define WSP 36    // Ws row pad (floats): bank = (4m + k) % 32, conflict-free
#define BSP 136   // Bs row pad (floats): bank = (8k + n) % 32, conflict-free
#define GSTAGE (128*WSP + 32*BSP)   // floats per stage = 4608 + 4352 = 8960

__global__ void __launch_bounds__(256) k_gemm(const float* __restrict__ W,
                                              const float* __restrict__ Xext,
                                              int useB) {
    extern __shared__ float smem[];
    int b  = blockIdx.z;
    int m0 = blockIdx.y * 128;
    int n0 = blockIdx.x * 128;
    int tid  = threadIdx.x;
    int warp = tid >> 5, lane = tid & 31;
    int wm = warp >> 2, wn = warp & 3;          // 2 x 4
    int r  = lane >> 2, c = lane & 3;

    const float* Xb = (useB ? (const float*)g_bufB : Xext) + (size_t)b*Cq*TVq;

    // loader indices (4 x float4 each for W and X per stage)
    int wi_m = tid >> 1;            // with i*128 added: m = (tid + i*256)>>3 ... compute inline
    (void)wi_m;

    uint32_t sbase = (uint32_t)__cvta_generic_to_shared(smem);

    float acc[4][4][4];
    #pragma unroll
    for (int i = 0; i < 4; i++)
        #pragma unroll
        for (int j = 0; j < 4; j++)
            #pragma unroll
            for (int q = 0; q < 4; q++) acc[i][j][q] = 0.f;

    // prologue: stage 0
    {
        int k0 = 0;
        uint32_t ws = sbase;                       // stage 0
        uint32_t bs = sbase + 128*WSP*4;
        #pragma unroll
        for (int i = 0; i < 4; i++) {
            int idx = tid + i*256;
            int m = idx >> 3, kq = idx & 7;
            cpasync16(ws + (m*WSP + kq*4)*4, &W[(size_t)(m0 + m)*Cq + k0 + kq*4]);
        }
        #pragma unroll
        for (int i = 0; i < 4; i++) {
            int idx = tid + i*256;
            int k = idx >> 5, nq = idx & 31;
            cpasync16(bs + (k*BSP + nq*4)*4, &Xb[(size_t)(k0 + k)*TVq + n0 + nq*4]);
        }
        CP_COMMIT();
    }

    for (int kt = 0; kt < 8; kt++) {
        CP_WAIT0();
        __syncthreads();

        if (kt + 1 < 8) {
            int k0 = (kt + 1) * 32;
            int s  = (kt + 1) & 1;
            uint32_t ws = sbase + s*GSTAGE*4;
            uint32_t bs = ws + 128*WSP*4;
            #pragma unroll
            for (int i = 0; i < 4; i++) {
                int idx = tid + i*256;
                int m = idx >> 3, kq = idx & 7;
                cpasync16(ws + (m*WSP + kq*4)*4, &W[(size_t)(m0 + m)*Cq + k0 + kq*4]);
            }
            #pragma unroll
            for (int i = 0; i < 4; i++) {
                int idx = tid + i*256;
                int k = idx >> 5, nq = idx & 31;
                cpasync16(bs + (k*BSP + nq*4)*4, &Xb[(size_t)(k0 + k)*TVq + n0 + nq*4]);
            }
            CP_COMMIT();
        }

        const float* ws = smem + (kt & 1)*GSTAGE;
        const float* bs = ws + 128*WSP;

        #pragma unroll
        for (int kq = 0; kq < 32; kq += 8) {
            uint32_t Af[4][4];
            #pragma unroll
            for (int mi = 0; mi < 4; mi++) {
                const float* p = ws + (wm*64 + mi*16 + r)*WSP + kq + c;
                Af[mi][0] = fbits(p[0]);
                Af[mi][1] = fbits(p[8*WSP]);
                Af[mi][2] = fbits(p[4]);
                Af[mi][3] = fbits(p[8*WSP + 4]);
            }
            uint32_t Bf[4][2];
            #pragma unroll
            for (int ni = 0; ni < 4; ni++) {
                const float* q = bs + (kq + c)*BSP + wn*32 + ni*8 + r;
                Bf[ni][0] = fbits(q[0]);
                Bf[ni][1] = fbits(q[4*BSP]);
            }
            #pragma unroll
            for (int mi = 0; mi < 4; mi++)
                #pragma unroll
                for (int ni = 0; ni < 4; ni++)
                    mma_tf32(acc[mi][ni], Af[mi][0], Af[mi][1], Af[mi][2], Af[mi][3],
                             Bf[ni][0], Bf[ni][1]);
        }
    }

    float* Yb = g_bufA + (size_t)b*Oq*TVq;
    #pragma unroll
    for (int mi = 0; mi < 4; mi++) {
        int row = m0 + wm*64 + mi*16 + r;
        #pragma unroll
        for (int ni = 0; ni < 4; ni++) {
            int col = n0 + wn*32 + ni*8 + 2*c;
            *(float2*)&Yb[(size_t)row*TVq + col]       = make_float2(acc[mi][ni][0], acc[mi][ni][1]);
            *(float2*)&Yb[(size_t)(row + 8)*TVq + col] = make_float2(acc[mi][ni][2], acc[mi][ni][3]);
        }
    }
}

// per-channel sum & sumsq of g_bufA
__global__ void k_stats(int slot) {
    int o = blockIdx.x, b = blockIdx.y, tid = threadIdx.x;
    const float* p = g_bufA + (size_t)(b*Oq + o)*TVq;
    float s = 0.f, q = 0.f;
    for (int i = tid; i < TVq; i += 256) { float y = p[i]; s += y; q = fmaf(y, y, q); }
    __shared__ float ss[256], qq[256];
    ss[tid] = s; qq[tid] = q;
    __syncthreads();
    for (int st = 128; st > 0; st >>= 1) {
        if (tid < st) { ss[tid] += ss[tid + st]; qq[tid] += qq[tid + st]; }
        __syncthreads();
    }
    if (tid == 0) {
        atomicAdd(&g_stats[slot*Oq + o],     ss[0]);
        atomicAdd(&g_stats[(slot+1)*Oq + o], qq[0]);
    }
}

// ---------------- stage5: h = relu(BN(bufA)); A = M + alpha*tanh(x1-x2); bufB = h @ A
// TF32 MMA: M=128(t), N=64(w), K=64(v). 8 warps 4(m) x 2(n), warp tile 32x32.
#define HSP 68    // hs pad: bank (4t + v) % 32 conflict-free
#define ASP 72    // As pad: bank (8v + w) % 32 conflict-free
#define S5SMEM (128*HSP + 64*ASP)   // 8704 + 4608 = 13312 floats

__global__ void __launch_bounds__(256) k_stage5(const float* __restrict__ alpha_p,
                                                const float* __restrict__ gamma,
                                                const float* __restrict__ beta) {
    extern __shared__ float smem[];
    float* hs = smem;               // [128][HSP]
    float* As = smem + 128*HSP;     // [64][ASP]

    int bx = blockIdx.x;            // b*256 + o,  o = k*32 + c
    int b = bx >> 8, o = bx & 255, k = o >> 5;
    int tid  = threadIdx.x;
    int warp = tid >> 5, lane = tid & 31;
    int wm = warp >> 1, wn = warp & 1;
    int r  = lane >> 2, c = lane & 3;

    float mean  = g_stats[o]      * (1.f/CNT);
    float var   = g_stats[Oq + o] * (1.f/CNT) - mean*mean;
    float scale = gamma[o] * rsqrtf(var + 1e-5f);
    float shift = beta[o] - mean*scale;

    const float4* src = (const float4*)(g_bufA + (size_t)bx*TVq);
    for (int i = tid; i < TVq/4; i += 256) {
        float4 y = src[i];
        int t = (i*4) >> 6, v = (i*4) & 63;
        float4 h;
        h.x = fmaxf(fmaf(y.x, scale, shift), 0.f);
        h.y = fmaxf(fmaf(y.y, scale, shift), 0.f);
        h.z = fmaxf(fmaf(y.z, scale, shift), 0.f);
        h.w = fmaxf(fmaf(y.w, scale, shift), 0.f);
        *(float4*)&hs[t*HSP + v] = h;
    }

    float alpha = alpha_p[0];
    const float* x1r = g_x1 + bx*Vq;
    const float* x2r = g_x2 + bx*Vq;
    const float* Mp  = g_M + (size_t)(b*Kq + k)*Vq*Vq;
    for (int i = tid; i < Vq*Vq; i += 256) {
        int v = i >> 6, w = i & 63;
        As[v*ASP + w] = Mp[i] + alpha * tanhf(x1r[v] - x2r[w]);
    }
    __syncthreads();

    float acc[2][4][4];
    #pragma unroll
    for (int i = 0; i < 2; i++)
        #pragma unroll
        for (int j = 0; j < 4; j++)
            #pragma unroll
            for (int q = 0; q < 4; q++) acc[i][j][q] = 0.f;

    #pragma unroll
    for (int kq = 0; kq < 64; kq += 8) {
        uint32_t Af[2][4];
        #pragma unroll
        for (int mi = 0; mi < 2; mi++) {
            const float* p = hs + (wm*32 + mi*16 + r)*HSP + kq + c;
            Af[mi][0] = fbits(p[0]);
            Af[mi][1] = fbits(p[8*HSP]);
            Af[mi][2] = fbits(p[4]);
            Af[mi][3] = fbits(p[8*HSP + 4]);
        }
        uint32_t Bf[4][2];
        #pragma unroll
        for (int ni = 0; ni < 4; ni++) {
            const float* q = As + (kq + c)*ASP + wn*32 + ni*8 + r;
            Bf[ni][0] = fbits(q[0]);
            Bf[ni][1] = fbits(q[4*ASP]);
        }
        #pragma unroll
        for (int mi = 0; mi < 2; mi++)
            #pragma unroll
            for (int ni = 0; ni < 4; ni++)
                mma_tf32(acc[mi][ni], Af[mi][0], Af[mi][1], Af[mi][2], Af[mi][3],
                         Bf[ni][0], Bf[ni][1]);
    }

    float* dst = g_bufB + (size_t)bx*TVq;
    #pragma unroll
    for (int mi = 0; mi < 2; mi++) {
        int row = wm*32 + mi*16 + r;
        #pragma unroll
        for (int ni = 0; ni < 4; ni++) {
            int col = wn*32 + ni*8 + 2*c;
            *(float2*)&dst[row*Vq + col]       = make_float2(acc[mi][ni][0], acc[mi][ni][1]);
            *(float2*)&dst[(row + 8)*Vq + col] = make_float2(acc[mi][ni][2], acc[mi][ni][3]);
        }
    }
}

// out = relu(BN(bufA) + x)
__global__ void k_out(const float* __restrict__ x,
                      const float* __restrict__ gamma, const float* __restrict__ beta,
                      float* __restrict__ out) {
    size_t idx = (size_t)blockIdx.x * 256 + threadIdx.x;
    int o = (int)((idx >> 11) & 255);
    float mean  = g_stats[2*Oq + o] * (1.f/CNT);
    float var   = g_stats[3*Oq + o] * (1.f/CNT) - mean*mean;
    float scale = gamma[o] * rsqrtf(var + 1e-5f);
    float shift = beta[o] - mean*scale;
    float4 z  = ((const float4*)g_bufA)[idx];
    float4 xv = ((const float4*)x)[idx];
    float4 rr;
    rr.x = fmaxf(fmaf(z.x, scale, shift) + xv.x, 0.f);
    rr.y = fmaxf(fmaf(z.y, scale, shift) + xv.y, 0.f);
    rr.z = fmaxf(fmaf(z.z, scale, shift) + xv.z, 0.f);
    rr.w = fmaxf(fmaf(z.w, scale, shift) + xv.w, 0.f);
    ((float4*)out)[idx] = rr;
}

// ---------------- launch ----------------
extern "C" void kernel_launch(void* const* d_in, const int* in_sizes, int n_in,
                              void* d_out, int out_size) {
    const float* x       = (const float*)d_in[0];
    const float* A_param = (const float*)d_in[1];
    const float* alpha   = (const float*)d_in[2];
    const float* beta    = (const float*)d_in[3];
    const float* w1      = (const float*)d_in[4];
    const float* b1      = (const float*)d_in[5];
    const float* w2      = (const float*)d_in[6];
    const float* b2      = (const float*)d_in[7];
    const float* stem_w  = (const float*)d_in[8];
    const float* stem_g  = (const float*)d_in[10];
    const float* stem_be = (const float*)d_in[11];
    const float* head_w  = (const float*)d_in[12];
    const float* head_g  = (const float*)d_in[14];
    const float* head_be = (const float*)d_in[15];
    float* out = (float*)d_out;

    int gemm_smem   = 2 * GSTAGE * 4;   // 71680 bytes
    int stage5_smem = S5SMEM * 4;       // 53248 bytes
    cudaFuncSetAttribute(k_gemm,   cudaFuncAttributeMaxDynamicSharedMemorySize, gemm_smem);
    cudaFuncSetAttribute(k_stage5, cudaFuncAttributeMaxDynamicSharedMemorySize, stage5_smem);

    k_zero<<<1, 1024>>>();
    k_meanT<<<Bq*Cq, Vq>>>(x);
    k_x1x2<<<Bq*Oq, Vq>>>(w1, b1, w2, b2);
    k_adj<<<Bq*Kq, 256>>>(A_param, beta);

    // stem conv (bias cancels in BN)
    k_gemm<<<dim3(TVq/128, Oq/128, Bq), 256, gemm_smem>>>(stem_w, x, 0);
    k_stats<<<dim3(Oq, Bq), 256>>>(0);

    // BN+relu fused into graph matmul (tensor cores)
    k_stage5<<<Bq*Oq, 256, stage5_smem>>>(alpha, stem_g, stem_be);

    // head conv
    k_gemm<<<dim3(TVq/128, Oq/128, Bq), 256, gemm_smem>>>(head_w, (const float*)0, 1);
    k_stats<<<dim3(Oq, Bq), 256>>>(2);

    k_out<<<(Bq*Oq*TVq/4)/256, 256>>>(x, head_g, head_be, out);
}

// round 3
// speedup vs baseline: 2.5479x; 1.0671x over previous
#include <cuda_runtime.h>
#include <cmath>
#include <cstdint>

#define Bq 16
#define Cq 256
#define Tq 128
#define Vq 64
#define Kq 8
#define Oq 256
#define TVq 8192            // T*V
#define CNT 131072          // B*T*V  (per-channel BN count)

// ---------------- scratch ----------------
__device__ float g_tp[Bq*Cq*Vq];
__device__ float g_x1[Bq*Oq*Vq];
__device__ float g_x2[Bq*Oq*Vq];
__device__ float g_M [Bq*Kq*Vq*Vq];
__device__ float g_bufA[Bq*Oq*TVq];
__device__ float g_bufB[Bq*Oq*TVq];
__device__ float g_stats[4*Oq];

// ---------------- helpers ----------------
__device__ __forceinline__ void mma_tf32(float c[4],
                                         uint32_t a0, uint32_t a1, uint32_t a2, uint32_t a3,
                                         uint32_t b0, uint32_t b1) {
    asm volatile(
        "mma.sync.aligned.m16n8k8.row.col.f32.tf32.tf32.f32 "
        "{%0,%1,%2,%3},{%4,%5,%6,%7},{%8,%9},{%0,%1,%2,%3};\n"
        : "+f"(c[0]), "+f"(c[1]), "+f"(c[2]), "+f"(c[3])
        : "r"(a0), "r"(a1), "r"(a2), "r"(a3), "r"(b0), "r"(b1));
}
__device__ __forceinline__ void cpasync16(uint32_t saddr, const void* g) {
    asm volatile("cp.async.cg.shared.global [%0], [%1], 16;\n" :: "r"(saddr), "l"(g));
}
#define CP_COMMIT() asm volatile("cp.async.commit_group;\n" ::: "memory")
#define CP_WAIT(n)  asm volatile("cp.async.wait_group %0;\n" :: "n"(n) : "memory")
__device__ __forceinline__ uint32_t fbits(float f) { return __float_as_uint(f); }

// ---------------- small kernels ----------------

__global__ void k_zero() {
    int i = threadIdx.x;
    if (i < 4*Oq) g_stats[i] = 0.f;
}

// tp[b,c,v] = mean_t x[b,c,t,v]  — 256 threads, coalesced
__global__ void k_meanT(const float* __restrict__ x) {
    int bc = blockIdx.x;
    int tid = threadIdx.x;
    int v = tid & 63, tq = tid >> 6;
    const float* p = x + (size_t)bc*TVq + tq*32*Vq + v;
    float s = 0.f;
    #pragma unroll 8
    for (int t = 0; t < 32; t++) s += p[t*Vq];
    __shared__ float sm[256];
    sm[tid] = s;
    __syncthreads();
    if (tid < 128) sm[tid] += sm[tid + 128];
    __syncthreads();
    if (tid < 64) g_tp[bc*Vq + tid] = (sm[tid] + sm[tid + 64]) * (1.f/Tq);
}

__global__ void k_x1x2(const float* __restrict__ w1, const float* __restrict__ b1,
                       const float* __restrict__ w2, const float* __restrict__ b2) {
    int bo = blockIdx.x;
    int b  = bo >> 8, o = bo & 255;
    int v  = threadIdx.x;
    const float* tp = g_tp + (size_t)b*Cq*Vq + v;
    float a1 = 0.f, a2 = 0.f;
    #pragma unroll 4
    for (int c = 0; c < Cq; c++) {
        float t = tp[c*Vq];
        a1 = fmaf(t, __ldg(&w1[o*Cq + c]), a1);
        a2 = fmaf(t, __ldg(&w2[o*Cq + c]), a2);
    }
    g_x1[bo*Vq + v] = a1 + b1[o];
    g_x2[bo*Vq + v] = a2 + b2[o];
}

__global__ void k_adj(const float* __restrict__ Ap, const float* __restrict__ beta_p) {
    __shared__ float x1s[32][Vq];
    __shared__ float x2s[32][Vq];
    __shared__ float S[Vq][Vq];
    int bk = blockIdx.x;
    int b = bk >> 3, k = bk & 7;
    int tid = threadIdx.x;

    for (int i = tid; i < 32*Vq; i += 256) {
        int c = i >> 6, v = i & 63;
        int row = (b*Oq + k*32 + c)*Vq + v;
        x1s[c][v] = g_x1[row];
        x2s[c][v] = g_x2[row];
    }
    __syncthreads();

    for (int i = tid; i < Vq*Vq; i += 256) {
        int v = i >> 6, w = i & 63;
        float s = 0.f;
        #pragma unroll
        for (int c = 0; c < 32; c++) s = fmaf(x1s[c][v], x2s[c][w], s);
        S[v][w] = s;
    }
    __syncthreads();

    if (tid < Vq) {
        int w = tid;
        float m = -1e30f;
        for (int v = 0; v < Vq; v++) m = fmaxf(m, S[v][w]);
        float sum = 0.f;
        for (int v = 0; v < Vq; v++) { float e = __expf(S[v][w] - m); S[v][w] = e; sum += e; }
        float scl = beta_p[0] / sum;
        for (int v = 0; v < Vq; v++) {
            g_M[((bk*Vq + v) << 6) + w] = Ap[((k*Vq + v) << 6) + w] + S[v][w]*scl;
        }
    }
}

// ---------------- TF32 GEMM, 128x256 block tile, 64x64 warp tile, 3-stage ----------------
// Y[b, m0+m, n0+n] = sum_c W[m,c] * X[b,c,n]; also accumulates per-channel BN stats.
#define WSP 36     // W smem row pad: bank (4m + k) conflict-free
#define BSPn 264   // X smem row pad: 264 % 32 == 8 -> bank (8c + r) conflict-free
#define WST (128*WSP)            // 4608 floats
#define XST (32*BSPn)            // 8448 floats
#define GSTAGE (WST + XST)       // 13056 floats = 52224 B
#define NSTAGE 3

__global__ void __launch_bounds__(256, 1) k_gemm(const float* __restrict__ W,
                                                 const float* __restrict__ Xext,
                                                 int useB, int slot) {
    extern __shared__ float smem[];
    int b  = blockIdx.z;
    int m0 = blockIdx.y * 128;
    int n0 = blockIdx.x * 256;
    int tid  = threadIdx.x;
    int warp = tid >> 5, lane = tid & 31;
    int wm = warp >> 2, wn = warp & 3;          // 2 x 4 warps -> warp tile 64(m) x 64(n)
    int r  = lane >> 2, c = lane & 3;

    const float* Xb = (useB ? (const float*)g_bufB : Xext) + (size_t)b*Cq*TVq;
    uint32_t sbase = (uint32_t)__cvta_generic_to_shared(smem);

    float acc[4][8][4];
    #pragma unroll
    for (int i = 0; i < 4; i++)
        #pragma unroll
        for (int j = 0; j < 8; j++)
            #pragma unroll
            for (int q = 0; q < 4; q++) acc[i][j][q] = 0.f;

    // stage loader
    auto load_stage = [&](int kt, int s) {
        int k0 = kt * 32;
        uint32_t ws = sbase + (uint32_t)s*GSTAGE*4;
        uint32_t xs = ws + WST*4;
        #pragma unroll
        for (int i = 0; i < 4; i++) {                 // W: 128x32
            int idx = tid + i*256;
            int m = idx >> 3, kq = idx & 7;
            cpasync16(ws + (m*WSP + kq*4)*4, &W[(size_t)(m0 + m)*Cq + k0 + kq*4]);
        }
        #pragma unroll
        for (int i = 0; i < 8; i++) {                 // X: 32x256
            int idx = tid + i*256;
            int k = idx >> 6, nq = idx & 63;
            cpasync16(xs + (k*BSPn + nq*4)*4, &Xb[(size_t)(k0 + k)*TVq + n0 + nq*4]);
        }
        CP_COMMIT();
    };

    load_stage(0, 0);
    load_stage(1, 1);

    for (int kt = 0; kt < 8; kt++) {
        CP_WAIT(1);
        __syncthreads();
        if (kt + 2 < 8) load_stage(kt + 2, (kt + 2) % NSTAGE);

        const float* ws = smem + (kt % NSTAGE)*GSTAGE;
        const float* xs = ws + WST;

        #pragma unroll
        for (int kq = 0; kq < 32; kq += 8) {
            uint32_t Af[4][4];
            #pragma unroll
            for (int mi = 0; mi < 4; mi++) {
                const float* p = ws + (wm*64 + mi*16 + r)*WSP + kq + c;
                Af[mi][0] = fbits(p[0]);
                Af[mi][1] = fbits(p[8*WSP]);
                Af[mi][2] = fbits(p[4]);
                Af[mi][3] = fbits(p[8*WSP + 4]);
            }
            uint32_t Bf[8][2];
            #pragma unroll
            for (int ni = 0; ni < 8; ni++) {
                const float* q = xs + (kq + c)*BSPn + wn*64 + ni*8 + r;
                Bf[ni][0] = fbits(q[0]);
                Bf[ni][1] = fbits(q[4*BSPn]);
            }
            #pragma unroll
            for (int mi = 0; mi < 4; mi++)
                #pragma unroll
                for (int ni = 0; ni < 8; ni++)
                    mma_tf32(acc[mi][ni], Af[mi][0], Af[mi][1], Af[mi][2], Af[mi][3],
                             Bf[ni][0], Bf[ni][1]);
        }
        __syncthreads();
    }

    // epilogue: store + fused BN stats (sum, sumsq per channel row)
    float* Yb = g_bufA + (size_t)b*Oq*TVq;
    #pragma unroll
    for (int mi = 0; mi < 4; mi++) {
        #pragma unroll
        for (int h = 0; h < 2; h++) {
            int row = m0 + wm*64 + mi*16 + h*8 + r;
            float s = 0.f, q = 0.f;
            #pragma unroll
            for (int ni = 0; ni < 8; ni++) {
                float v0 = acc[mi][ni][2*h], v1 = acc[mi][ni][2*h + 1];
                s += v0 + v1;
                q  = fmaf(v0, v0, fmaf(v1, v1, q));
                int col = n0 + wn*64 + ni*8 + 2*c;
                *(float2*)&Yb[(size_t)row*TVq + col] = make_float2(v0, v1);
            }
            // reduce over the 4 column-lanes (same r, different c = low 2 lane bits)
            s += __shfl_xor_sync(0xffffffffu, s, 1);
            s += __shfl_xor_sync(0xffffffffu, s, 2);
            q += __shfl_xor_sync(0xffffffffu, q, 1);
            q += __shfl_xor_sync(0xffffffffu, q, 2);
            if (c == 0) {
                atomicAdd(&g_stats[slot*Oq + row],     s);
                atomicAdd(&g_stats[(slot+1)*Oq + row], q);
            }
        }
    }
}

// ---------------- stage5 (unchanged core) ----------------
#define HSP 68
#define ASP 72
#define S5SMEM (128*HSP + 64*ASP)

__global__ void __launch_bounds__(256) k_stage5(const float* __restrict__ alpha_p,
                                                const float* __restrict__ gamma,
                                                const float* __restrict__ beta) {
    extern __shared__ float smem[];
    float* hs = smem;
    float* As = smem + 128*HSP;

    int bx = blockIdx.x;
    int b = bx >> 8, o = bx & 255, k = o >> 5;
    int tid  = threadIdx.x;
    int warp = tid >> 5, lane = tid & 31;
    int wm = warp >> 1, wn = warp & 1;
    int r  = lane >> 2, c = lane & 3;

    float mean  = g_stats[o]      * (1.f/CNT);
    float var   = g_stats[Oq + o] * (1.f/CNT) - mean*mean;
    float scale = gamma[o] * rsqrtf(var + 1e-5f);
    float shift = beta[o] - mean*scale;

    const float4* src = (const float4*)(g_bufA + (size_t)bx*TVq);
    for (int i = tid; i < TVq/4; i += 256) {
        float4 y = src[i];
        int t = (i*4) >> 6, v = (i*4) & 63;
        float4 h;
        h.x = fmaxf(fmaf(y.x, scale, shift), 0.f);
        h.y = fmaxf(fmaf(y.y, scale, shift), 0.f);
        h.z = fmaxf(fmaf(y.z, scale, shift), 0.f);
        h.w = fmaxf(fmaf(y.w, scale, shift), 0.f);
        *(float4*)&hs[t*HSP + v] = h;
    }

    float alpha = alpha_p[0];
    const float* x1r = g_x1 + bx*Vq;
    const float* x2r = g_x2 + bx*Vq;
    const float* Mp  = g_M + (size_t)(b*Kq + k)*Vq*Vq;
    for (int i = tid; i < Vq*Vq; i += 256) {
        int v = i >> 6, w = i & 63;
        As[v*ASP + w] = Mp[i] + alpha * tanhf(x1r[v] - x2r[w]);
    }
    __syncthreads();

    float acc[2][4][4];
    #pragma unroll
    for (int i = 0; i < 2; i++)
        #pragma unroll
        for (int j = 0; j < 4; j++)
            #pragma unroll
            for (int q = 0; q < 4; q++) acc[i][j][q] = 0.f;

    #pragma unroll
    for (int kq = 0; kq < 64; kq += 8) {
        uint32_t Af[2][4];
        #pragma unroll
        for (int mi = 0; mi < 2; mi++) {
            const float* p = hs + (wm*32 + mi*16 + r)*HSP + kq + c;
            Af[mi][0] = fbits(p[0]);
            Af[mi][1] = fbits(p[8*HSP]);
            Af[mi][2] = fbits(p[4]);
            Af[mi][3] = fbits(p[8*HSP + 4]);
        }
        uint32_t Bf[4][2];
        #pragma unroll
        for (int ni = 0; ni < 4; ni++) {
            const float* q = As + (kq + c)*ASP + wn*32 + ni*8 + r;
            Bf[ni][0] = fbits(q[0]);
            Bf[ni][1] = fbits(q[4*ASP]);
        }
        #pragma unroll
        for (int mi = 0; mi < 2; mi++)
            #pragma unroll
            for (int ni = 0; ni < 4; ni++)
                mma_tf32(acc[mi][ni], Af[mi][0], Af[mi][1], Af[mi][2], Af[mi][3],
                         Bf[ni][0], Bf[ni][1]);
    }

    float* dst = g_bufB + (size_t)bx*TVq;
    #pragma unroll
    for (int mi = 0; mi < 2; mi++) {
        int row = wm*32 + mi*16 + r;
        #pragma unroll
        for (int ni = 0; ni < 4; ni++) {
            int col = wn*32 + ni*8 + 2*c;
            *(float2*)&dst[row*Vq + col]       = make_float2(acc[mi][ni][0], acc[mi][ni][1]);
            *(float2*)&dst[(row + 8)*Vq + col] = make_float2(acc[mi][ni][2], acc[mi][ni][3]);
        }
    }
}

// out = relu(BN(bufA) + x)
__global__ void k_out(const float* __restrict__ x,
                      const float* __restrict__ gamma, const float* __restrict__ beta,
                      float* __restrict__ out) {
    size_t idx = (size_t)blockIdx.x * 256 + threadIdx.x;
    int o = (int)((idx >> 11) & 255);
    float mean  = g_stats[2*Oq + o] * (1.f/CNT);
    float var   = g_stats[3*Oq + o] * (1.f/CNT) - mean*mean;
    float scale = gamma[o] * rsqrtf(var + 1e-5f);
    float shift = beta[o] - mean*scale;
    float4 z  = ((const float4*)g_bufA)[idx];
    float4 xv = ((const float4*)x)[idx];
    float4 rr;
    rr.x = fmaxf(fmaf(z.x, scale, shift) + xv.x, 0.f);
    rr.y = fmaxf(fmaf(z.y, scale, shift) + xv.y, 0.f);
    rr.z = fmaxf(fmaf(z.z, scale, shift) + xv.z, 0.f);
    rr.w = fmaxf(fmaf(z.w, scale, shift) + xv.w, 0.f);
    ((float4*)out)[idx] = rr;
}

// ---------------- launch ----------------
extern "C" void kernel_launch(void* const* d_in, const int* in_sizes, int n_in,
                              void* d_out, int out_size) {
    const float* x       = (const float*)d_in[0];
    const float* A_param = (const float*)d_in[1];
    const float* alpha   = (const float*)d_in[2];
    const float* beta    = (const float*)d_in[3];
    const float* w1      = (const float*)d_in[4];
    const float* b1      = (const float*)d_in[5];
    const float* w2      = (const float*)d_in[6];
    const float* b2      = (const float*)d_in[7];
    const float* stem_w  = (const float*)d_in[8];
    const float* stem_g  = (const float*)d_in[10];
    const float* stem_be = (const float*)d_in[11];
    const float* head_w  = (const float*)d_in[12];
    const float* head_g  = (const float*)d_in[14];
    const float* head_be = (const float*)d_in[15];
    float* out = (float*)d_out;

    int gemm_smem   = NSTAGE * GSTAGE * 4;   // 156672 bytes
    int stage5_smem = S5SMEM * 4;            // 53248 bytes
    cudaFuncSetAttribute(k_gemm,   cudaFuncAttributeMaxDynamicSharedMemorySize, gemm_smem);
    cudaFuncSetAttribute(k_stage5, cudaFuncAttributeMaxDynamicSharedMemorySize, stage5_smem);

    k_zero<<<1, 1024>>>();
    k_meanT<<<Bq*Cq, 256>>>(x);
    k_x1x2<<<Bq*Oq, Vq>>>(w1, b1, w2, b2);
    k_adj<<<Bq*Kq, 256>>>(A_param, beta);

    // stem conv + fused BN stats (bias cancels in BN)
    k_gemm<<<dim3(TVq/256, Oq/128, Bq), 256, gemm_smem>>>(stem_w, x, 0, 0);

    // BN+relu fused into graph matmul (tensor cores)
    k_stage5<<<Bq*Oq, 256, stage5_smem>>>(alpha, stem_g, stem_be);

    // head conv + fused BN stats
    k_gemm<<<dim3(TVq/256, Oq/128, Bq), 256, gemm_smem>>>(head_w, (const float*)0, 1, 2);

    k_out<<<(Bq*Oq*TVq/4)/256, 256>>>(x, head_g, head_be, out);
}

// round 4
// speedup vs baseline: 3.2191x; 1.2634x over previous
#include <cuda_runtime.h>
#include <cuda_fp16.h>
#include <cmath>
#include <cstdint>

#define Bq 16
#define Cq 256
#define Tq 128
#define Vq 64
#define Kq 8
#define Oq 256
#define TVq 8192
#define CNT 131072

// ---------------- scratch ----------------
__device__ float  g_tp[Bq*Cq*Vq];
__device__ float  g_x1[Bq*Oq*Vq];
__device__ float  g_x2[Bq*Oq*Vq];
__device__ float  g_M [Bq*Kq*Vq*Vq];
__device__ float  g_stats[4*Oq];
__device__ __half g_xh  [(size_t)Bq*Cq*TVq];   // fp16 copy of x
__device__ __half g_bufAh[(size_t)Bq*Oq*TVq];  // stem out y / head out z (fp16)
__device__ __half g_bufBh[(size_t)Bq*Oq*TVq];  // stage5 out (fp16)
__device__ __half g_wh[2*Oq*Cq];               // fp16 stem_w, head_w

// ---------------- helpers ----------------
__device__ __forceinline__ void mma_f16(float c[4],
                                        uint32_t a0, uint32_t a1, uint32_t a2, uint32_t a3,
                                        uint32_t b0, uint32_t b1) {
    asm volatile(
        "mma.sync.aligned.m16n8k16.row.col.f32.f16.f16.f32 "
        "{%0,%1,%2,%3},{%4,%5,%6,%7},{%8,%9},{%0,%1,%2,%3};\n"
        : "+f"(c[0]), "+f"(c[1]), "+f"(c[2]), "+f"(c[3])
        : "r"(a0), "r"(a1), "r"(a2), "r"(a3), "r"(b0), "r"(b1));
}
__device__ __forceinline__ void ldsm_x4(uint32_t& r0, uint32_t& r1, uint32_t& r2, uint32_t& r3,
                                        uint32_t addr) {
    asm volatile("ldmatrix.sync.aligned.m8n8.x4.shared.b16 {%0,%1,%2,%3}, [%4];\n"
                 : "=r"(r0), "=r"(r1), "=r"(r2), "=r"(r3) : "r"(addr));
}
__device__ __forceinline__ void ldsm_x4_t(uint32_t& r0, uint32_t& r1, uint32_t& r2, uint32_t& r3,
                                          uint32_t addr) {
    asm volatile("ldmatrix.sync.aligned.m8n8.x4.trans.shared.b16 {%0,%1,%2,%3}, [%4];\n"
                 : "=r"(r0), "=r"(r1), "=r"(r2), "=r"(r3) : "r"(addr));
}
__device__ __forceinline__ void cpasync16(uint32_t saddr, const void* g) {
    asm volatile("cp.async.cg.shared.global [%0], [%1], 16;\n" :: "r"(saddr), "l"(g));
}
#define CP_COMMIT() asm volatile("cp.async.commit_group;\n" ::: "memory")
#define CP_WAIT(n)  asm volatile("cp.async.wait_group %0;\n" :: "n"(n) : "memory")

// ---------------- small kernels ----------------
__global__ void k_zero() {
    int i = threadIdx.x;
    if (i < 4*Oq) g_stats[i] = 0.f;
}

__global__ void k_wconv(const float* __restrict__ w1, const float* __restrict__ w2) {
    int i = blockIdx.x*256 + threadIdx.x;           // 65536 total
    g_wh[i]            = __float2half(w1[i]);
    g_wh[Oq*Cq + i]    = __float2half(w2[i]);
}

// x -> fp16 copy + per-(b,c) mean over T
__global__ void k_meanT(const float* __restrict__ x) {
    int bc = blockIdx.x;
    int tid = threadIdx.x;
    __shared__ float red[64];
    if (tid < 64) red[tid] = 0.f;
    __syncthreads();
    const float4* p = (const float4*)(x + (size_t)bc*TVq);
    __half* xo = g_xh + (size_t)bc*TVq;
    float s0=0.f, s1=0.f, s2=0.f, s3=0.f;
    int v0 = (tid*4) & 63;
    #pragma unroll
    for (int i = 0; i < 8; i++) {
        int e = tid + i*256;
        float4 f = p[e];
        s0 += f.x; s1 += f.y; s2 += f.z; s3 += f.w;
        ((__half2*)xo)[e*2]     = __floats2half2_rn(f.x, f.y);
        ((__half2*)xo)[e*2 + 1] = __floats2half2_rn(f.z, f.w);
    }
    atomicAdd(&red[v0],   s0);
    atomicAdd(&red[v0+1], s1);
    atomicAdd(&red[v0+2], s2);
    atomicAdd(&red[v0+3], s3);
    __syncthreads();
    if (tid < 64) g_tp[bc*Vq + tid] = red[tid] * (1.f/Tq);
}

__global__ void k_x1x2(const float* __restrict__ w1, const float* __restrict__ b1,
                       const float* __restrict__ w2, const float* __restrict__ b2) {
    int bo = blockIdx.x;
    int b  = bo >> 8, o = bo & 255;
    int v  = threadIdx.x;
    const float* tp = g_tp + (size_t)b*Cq*Vq + v;
    float a1 = 0.f, a2 = 0.f;
    #pragma unroll 4
    for (int c = 0; c < Cq; c++) {
        float t = tp[c*Vq];
        a1 = fmaf(t, __ldg(&w1[o*Cq + c]), a1);
        a2 = fmaf(t, __ldg(&w2[o*Cq + c]), a2);
    }
    g_x1[bo*Vq + v] = a1 + b1[o];
    g_x2[bo*Vq + v] = a2 + b2[o];
}

__global__ void k_adj(const float* __restrict__ Ap, const float* __restrict__ beta_p) {
    __shared__ float x1s[32][Vq];
    __shared__ float x2s[32][Vq];
    __shared__ float S[Vq][Vq];
    int bk = blockIdx.x;
    int b = bk >> 3, k = bk & 7;
    int tid = threadIdx.x;

    for (int i = tid; i < 32*Vq; i += 256) {
        int c = i >> 6, v = i & 63;
        int row = (b*Oq + k*32 + c)*Vq + v;
        x1s[c][v] = g_x1[row];
        x2s[c][v] = g_x2[row];
    }
    __syncthreads();
    for (int i = tid; i < Vq*Vq; i += 256) {
        int v = i >> 6, w = i & 63;
        float s = 0.f;
        #pragma unroll
        for (int c = 0; c < 32; c++) s = fmaf(x1s[c][v], x2s[c][w], s);
        S[v][w] = s;
    }
    __syncthreads();
    if (tid < Vq) {
        int w = tid;
        float m = -1e30f;
        for (int v = 0; v < Vq; v++) m = fmaxf(m, S[v][w]);
        float sum = 0.f;
        for (int v = 0; v < Vq; v++) { float e = __expf(S[v][w] - m); S[v][w] = e; sum += e; }
        float scl = beta_p[0] / sum;
        for (int v = 0; v < Vq; v++)
            g_M[((bk*Vq + v) << 6) + w] = Ap[((k*Vq + v) << 6) + w] + S[v][w]*scl;
    }
}

// ---------------- fp16 GEMM: Y = W(128m) @ X(256n), k=256, fused BN stats ----------------
#define WSPh 40     // 80B rows: 5 x 16B units (odd -> LDSM conflict-free)
#define XSPh 264    // 528B rows: 33 units (odd)
#define WSTh (128*WSPh)           // 5120 halfs
#define XSTh (32*XSPh)            // 8448 halfs
#define GSTAGEh (WSTh + XSTh)     // 13568 halfs = 27136 B
#define NSTAGE 3

__global__ void __launch_bounds__(256, 1) k_gemm(const __half* __restrict__ Wh,
                                                 const __half* __restrict__ Xg,
                                                 int slot) {
    extern __shared__ __align__(16) char smraw[];
    __half* smem = (__half*)smraw;
    int b  = blockIdx.z;
    int m0 = blockIdx.y * 128;
    int n0 = blockIdx.x * 256;
    int tid  = threadIdx.x;
    int warp = tid >> 5, lane = tid & 31;
    int wm = warp >> 2, wn = warp & 3;           // 2 x 4 warps, warp tile 64x64
    int r  = lane >> 2, c = lane & 3;
    int l16 = lane & 15, lh = lane >> 4;

    const __half* Xb = Xg + (size_t)b*Cq*TVq;
    uint32_t sbase = (uint32_t)__cvta_generic_to_shared(smem);

    float acc[4][8][4];
    #pragma unroll
    for (int i = 0; i < 4; i++)
        #pragma unroll
        for (int j = 0; j < 8; j++)
            #pragma unroll
            for (int q = 0; q < 4; q++) acc[i][j][q] = 0.f;

    auto load_stage = [&](int kt, int s) {
        int k0 = kt * 32;
        uint32_t ws = sbase + (uint32_t)s*GSTAGEh*2;
        uint32_t xs = ws + WSTh*2;
        #pragma unroll
        for (int i = 0; i < 2; i++) {                  // W: 128 x 32
            int idx = tid + i*256;
            int m = idx >> 2, ch = idx & 3;
            cpasync16(ws + (m*WSPh + ch*8)*2, &Wh[(size_t)(m0 + m)*Cq + k0 + ch*8]);
        }
        #pragma unroll
        for (int i = 0; i < 4; i++) {                  // X: 32 x 256
            int idx = tid + i*256;
            int k = idx >> 5, ch = idx & 31;
            cpasync16(xs + (k*XSPh + ch*8)*2, &Xb[(size_t)(k0 + k)*TVq + n0 + ch*8]);
        }
        CP_COMMIT();
    };

    load_stage(0, 0);
    load_stage(1, 1);

    for (int kt = 0; kt < 8; kt++) {
        CP_WAIT(1);
        __syncthreads();
        if (kt + 2 < 8) load_stage(kt + 2, (kt + 2) % NSTAGE);

        uint32_t ws = sbase + (uint32_t)(kt % NSTAGE)*GSTAGEh*2;
        uint32_t xs = ws + WSTh*2;

        #pragma unroll
        for (int ks = 0; ks < 2; ks++) {
            uint32_t Af[4][4];
            #pragma unroll
            for (int mi = 0; mi < 4; mi++)
                ldsm_x4(Af[mi][0], Af[mi][1], Af[mi][2], Af[mi][3],
                        ws + ((wm*64 + mi*16 + l16)*WSPh + ks*16 + 8*lh)*2);
            uint32_t Bf[4][4];
            #pragma unroll
            for (int p = 0; p < 4; p++)
                ldsm_x4_t(Bf[p][0], Bf[p][1], Bf[p][2], Bf[p][3],
                          xs + ((ks*16 + l16)*XSPh + wn*64 + p*16 + 8*lh)*2);
            #pragma unroll
            for (int mi = 0; mi < 4; mi++)
                #pragma unroll
                for (int p = 0; p < 4; p++) {
                    mma_f16(acc[mi][2*p],   Af[mi][0], Af[mi][1], Af[mi][2], Af[mi][3],
                            Bf[p][0], Bf[p][1]);
                    mma_f16(acc[mi][2*p+1], Af[mi][0], Af[mi][1], Af[mi][2], Af[mi][3],
                            Bf[p][2], Bf[p][3]);
                }
        }
        __syncthreads();
    }

    // epilogue: fp16 store + fused BN stats
    __half* Yb = g_bufAh + (size_t)b*Oq*TVq;
    #pragma unroll
    for (int mi = 0; mi < 4; mi++) {
        #pragma unroll
        for (int h = 0; h < 2; h++) {
            int row = m0 + wm*64 + mi*16 + h*8 + r;
            float s = 0.f, q = 0.f;
            #pragma unroll
            for (int ni = 0; ni < 8; ni++) {
                float v0 = acc[mi][ni][2*h], v1 = acc[mi][ni][2*h + 1];
                s += v0 + v1;
                q  = fmaf(v0, v0, fmaf(v1, v1, q));
                int col = n0 + wn*64 + ni*8 + 2*c;
                *(__half2*)&Yb[(size_t)row*TVq + col] = __floats2half2_rn(v0, v1);
            }
            s += __shfl_xor_sync(0xffffffffu, s, 1);
            s += __shfl_xor_sync(0xffffffffu, s, 2);
            q += __shfl_xor_sync(0xffffffffu, q, 1);
            q += __shfl_xor_sync(0xffffffffu, q, 2);
            if (c == 0) {
                atomicAdd(&g_stats[slot*Oq + row],     s);
                atomicAdd(&g_stats[(slot+1)*Oq + row], q);
            }
        }
    }
}

// ---------------- stage5: h = relu(BN(bufA)); A = M + a*tanh; bufB = h @ A (fp16 MMA) ----------------
#define HSPh 72     // 144B = 9 units (odd)
#define ASPh 72
#define S5H (128*HSPh + 64*ASPh)   // 9216 + 4608 = 13824 halfs = 27648 B

__global__ void __launch_bounds__(256) k_stage5(const float* __restrict__ alpha_p,
                                                const float* __restrict__ gamma,
                                                const float* __restrict__ beta) {
    extern __shared__ __align__(16) char smraw[];
    __half* hs = (__half*)smraw;            // [128][HSPh]
    __half* As = hs + 128*HSPh;             // [64][ASPh]

    int bx = blockIdx.x;
    int b = bx >> 8, o = bx & 255, k = o >> 5;
    int tid  = threadIdx.x;
    int warp = tid >> 5, lane = tid & 31;
    int wm = warp >> 1, wn = warp & 1;      // 4 x 2 warps, tile 32x32
    int r  = lane >> 2, c = lane & 3;
    int l16 = lane & 15, lh = lane >> 4;

    float mean  = g_stats[o]      * (1.f/CNT);
    float var   = g_stats[Oq + o] * (1.f/CNT) - mean*mean;
    float scale = gamma[o] * rsqrtf(var + 1e-5f);
    float shift = beta[o] - mean*scale;

    const __half* src = g_bufAh + (size_t)bx*TVq;
    for (int i = tid; i < TVq/8; i += 256) {         // 8 halfs per thread-iter
        int t = (i*8) >> 6, v = (i*8) & 63;
        const __half2* s2 = (const __half2*)(src + i*8);
        __half2 out[4];
        #pragma unroll
        for (int j = 0; j < 4; j++) {
            float2 f = __half22float2(s2[j]);
            out[j] = __floats2half2_rn(fmaxf(fmaf(f.x, scale, shift), 0.f),
                                       fmaxf(fmaf(f.y, scale, shift), 0.f));
        }
        *(uint2*)&hs[t*HSPh + v]     = *(uint2*)&out[0];
        *(uint2*)&hs[t*HSPh + v + 4] = *(uint2*)&out[2];
    }

    float alpha = alpha_p[0];
    const float* x1r = g_x1 + bx*Vq;
    const float* x2r = g_x2 + bx*Vq;
    const float* Mp  = g_M + (size_t)(b*Kq + k)*Vq*Vq;
    for (int i = tid; i < Vq*Vq; i += 256) {
        int v = i >> 6, w = i & 63;
        As[v*ASPh + w] = __float2half(Mp[i] + alpha * tanhf(x1r[v] - x2r[w]));
    }
    __syncthreads();

    uint32_t hsb = (uint32_t)__cvta_generic_to_shared(hs);
    uint32_t asb = (uint32_t)__cvta_generic_to_shared(As);

    float acc[2][4][4];
    #pragma unroll
    for (int i = 0; i < 2; i++)
        #pragma unroll
        for (int j = 0; j < 4; j++)
            #pragma unroll
            for (int q = 0; q < 4; q++) acc[i][j][q] = 0.f;

    #pragma unroll
    for (int ks = 0; ks < 4; ks++) {
        uint32_t Af[2][4];
        #pragma unroll
        for (int mi = 0; mi < 2; mi++)
            ldsm_x4(Af[mi][0], Af[mi][1], Af[mi][2], Af[mi][3],
                    hsb + ((wm*32 + mi*16 + l16)*HSPh + ks*16 + 8*lh)*2);
        uint32_t Bf[2][4];
        #pragma unroll
        for (int p = 0; p < 2; p++)
            ldsm_x4_t(Bf[p][0], Bf[p][1], Bf[p][2], Bf[p][3],
                      asb + ((ks*16 + l16)*ASPh + wn*32 + p*16 + 8*lh)*2);
        #pragma unroll
        for (int mi = 0; mi < 2; mi++)
            #pragma unroll
            for (int p = 0; p < 2; p++) {
                mma_f16(acc[mi][2*p],   Af[mi][0], Af[mi][1], Af[mi][2], Af[mi][3],
                        Bf[p][0], Bf[p][1]);
                mma_f16(acc[mi][2*p+1], Af[mi][0], Af[mi][1], Af[mi][2], Af[mi][3],
                        Bf[p][2], Bf[p][3]);
            }
    }

    __half* dst = g_bufBh + (size_t)bx*TVq;
    #pragma unroll
    for (int mi = 0; mi < 2; mi++) {
        int row = wm*32 + mi*16 + r;
        #pragma unroll
        for (int ni = 0; ni < 4; ni++) {
            int col = wn*32 + ni*8 + 2*c;
            *(__half2*)&dst[row*Vq + col]       = __floats2half2_rn(acc[mi][ni][0], acc[mi][ni][1]);
            *(__half2*)&dst[(row + 8)*Vq + col] = __floats2half2_rn(acc[mi][ni][2], acc[mi][ni][3]);
        }
    }
}

// out = relu(BN(z) + x),  z fp16
__global__ void k_out(const float* __restrict__ x,
                      const float* __restrict__ gamma, const float* __restrict__ beta,
                      float* __restrict__ out) {
    size_t i4 = (size_t)blockIdx.x * 256 + threadIdx.x;       // 4-element index
    int o = (int)((i4 >> 11) & 255);
    float mean  = g_stats[2*Oq + o] * (1.f/CNT);
    float var   = g_stats[3*Oq + o] * (1.f/CNT) - mean*mean;
    float scale = gamma[o] * rsqrtf(var + 1e-5f);
    float shift = beta[o] - mean*scale;
    const __half2* zp = (const __half2*)(g_bufAh) + i4*2;
    float2 z0 = __half22float2(zp[0]);
    float2 z1 = __half22float2(zp[1]);
    float4 xv = ((const float4*)x)[i4];
    float4 rr;
    rr.x = fmaxf(fmaf(z0.x, scale, shift) + xv.x, 0.f);
    rr.y = fmaxf(fmaf(z0.y, scale, shift) + xv.y, 0.f);
    rr.z = fmaxf(fmaf(z1.x, scale, shift) + xv.z, 0.f);
    rr.w = fmaxf(fmaf(z1.y, scale, shift) + xv.w, 0.f);
    ((float4*)out)[i4] = rr;
}

// ---------------- launch ----------------
extern "C" void kernel_launch(void* const* d_in, const int* in_sizes, int n_in,
                              void* d_out, int out_size) {
    const float* x       = (const float*)d_in[0];
    const float* A_param = (const float*)d_in[1];
    const float* alpha   = (const float*)d_in[2];
    const float* beta    = (const float*)d_in[3];
    const float* w1      = (const float*)d_in[4];
    const float* b1      = (const float*)d_in[5];
    const float* w2      = (const float*)d_in[6];
    const float* b2      = (const float*)d_in[7];
    const float* stem_w  = (const float*)d_in[8];
    const float* stem_g  = (const float*)d_in[10];
    const float* stem_be = (const float*)d_in[11];
    const float* head_w  = (const float*)d_in[12];
    const float* head_g  = (const float*)d_in[14];
    const float* head_be = (const float*)d_in[15];
    float* out = (float*)d_out;

    int gemm_smem   = NSTAGE * GSTAGEh * 2;   // 81408 B
    int stage5_smem = S5H * 2;                // 27648 B
    static int inited = 0;
    cudaFuncSetAttribute(k_gemm,   cudaFuncAttributeMaxDynamicSharedMemorySize, gemm_smem);
    cudaFuncSetAttribute(k_stage5, cudaFuncAttributeMaxDynamicSharedMemorySize, stage5_smem);
    (void)inited;

    // device weight halves
    __half* whp = nullptr;
    cudaGetSymbolAddress((void**)&whp, g_wh);

    k_zero<<<1, 1024>>>();
    k_wconv<<<Oq*Cq/256, 256>>>(stem_w, head_w);
    k_meanT<<<Bq*Cq, 256>>>(x);
    k_x1x2<<<Bq*Oq, Vq>>>(w1, b1, w2, b2);
    k_adj<<<Bq*Kq, 256>>>(A_param, beta);

    __half* xhp = nullptr;  cudaGetSymbolAddress((void**)&xhp, g_xh);
    __half* bBp = nullptr;  cudaGetSymbolAddress((void**)&bBp, g_bufBh);

    // stem conv + fused BN stats
    k_gemm<<<dim3(TVq/256, Oq/128, Bq), 256, gemm_smem>>>(whp, xhp, 0);

    // BN+relu + graph matmul
    k_stage5<<<Bq*Oq, 256, stage5_smem>>>(alpha, stem_g, stem_be);

    // head conv + fused BN stats
    k_gemm<<<dim3(TVq/256, Oq/128, Bq), 256, gemm_smem>>>(whp + Oq*Cq, bBp, 2);

    k_out<<<(int)(((size_t)Bq*Oq*TVq/4)/256), 256>>>(x, head_g, head_be, out);
}

// round 7
// speedup vs baseline: 3.6023x; 1.1190x over previous
#include <cuda_runtime.h>
#include <cuda_fp16.h>
#include <cmath>
#include <cstdint>

#define Bq 16
#define Cq 256
#define Tq 128
#define Vq 64
#define Kq 8
#define Oq 256
#define TVq 8192
#define CNT 131072
#define NBLK 1024            // GEMM blocks per launch = 64 * 16

// ---------------- scratch ----------------
__device__ float  g_tp[Bq*Cq*Vq];
__device__ float  g_x1[Bq*Oq*Vq];
__device__ float  g_x2[Bq*Oq*Vq];
__device__ float  g_M [Bq*Kq*Vq*Vq];
__device__ float  g_stats[4*Oq];
__device__ float  g_psum[2][NBLK][Oq];         // deterministic BN partials
__device__ float  g_psq [2][NBLK][Oq];
__device__ __half g_xh  [(size_t)Bq*Cq*TVq];   // fp16 copy of x
__device__ __half g_bufAh[(size_t)Bq*Oq*TVq];  // stem out y / head out z (fp16)
__device__ __half g_bufBh[(size_t)Bq*Oq*TVq];  // stage5 out (fp16)
__device__ __half g_wh[2*Oq*Cq];               // fp16 stem_w, head_w

// ---------------- helpers ----------------
__device__ __forceinline__ void mma_f16(float c[4],
                                        uint32_t a0, uint32_t a1, uint32_t a2, uint32_t a3,
                                        uint32_t b0, uint32_t b1) {
    asm volatile(
        "mma.sync.aligned.m16n8k16.row.col.f32.f16.f16.f32 "
        "{%0,%1,%2,%3},{%4,%5,%6,%7},{%8,%9},{%0,%1,%2,%3};\n"
        : "+f"(c[0]), "+f"(c[1]), "+f"(c[2]), "+f"(c[3])
        : "r"(a0), "r"(a1), "r"(a2), "r"(a3), "r"(b0), "r"(b1));
}
__device__ __forceinline__ void ldsm_x4(uint32_t& r0, uint32_t& r1, uint32_t& r2, uint32_t& r3,
                                        uint32_t addr) {
    asm volatile("ldmatrix.sync.aligned.m8n8.x4.shared.b16 {%0,%1,%2,%3}, [%4];\n"
                 : "=r"(r0), "=r"(r1), "=r"(r2), "=r"(r3) : "r"(addr));
}
__device__ __forceinline__ void ldsm_x4_t(uint32_t& r0, uint32_t& r1, uint32_t& r2, uint32_t& r3,
                                          uint32_t addr) {
    asm volatile("ldmatrix.sync.aligned.m8n8.x4.trans.shared.b16 {%0,%1,%2,%3}, [%4];\n"
                 : "=r"(r0), "=r"(r1), "=r"(r2), "=r"(r3) : "r"(addr));
}
__device__ __forceinline__ void cpasync16(uint32_t saddr, const void* g) {
    asm volatile("cp.async.cg.shared.global [%0], [%1], 16;\n" :: "r"(saddr), "l"(g));
}
#define CP_COMMIT() asm volatile("cp.async.commit_group;\n" ::: "memory")
#define CP_WAIT(n)  asm volatile("cp.async.wait_group %0;\n" :: "n"(n) : "memory")

// ---------------- init: fp16 weights only ----------------
__global__ void k_init(const float* __restrict__ w1, const float* __restrict__ w2) {
    int i = blockIdx.x*256 + threadIdx.x;           // 65536 total
    g_wh[i]         = __float2half(w1[i]);
    g_wh[Oq*Cq + i] = __float2half(w2[i]);
}

// x -> fp16 copy + per-(b,c) mean over T (shfl reduce, deterministic)
__global__ void k_meanT(const float* __restrict__ x) {
    int bc = blockIdx.x;
    int tid = threadIdx.x;
    int lane = tid & 31, warp = tid >> 5;
    __shared__ float red[8][64];
    const float4* p = (const float4*)(x + (size_t)bc*TVq);
    __half* xo = g_xh + (size_t)bc*TVq;
    float s0=0.f, s1=0.f, s2=0.f, s3=0.f;
    int v0 = (tid*4) & 63;
    #pragma unroll
    for (int i = 0; i < 8; i++) {
        int e = tid + i*256;
        float4 f = p[e];
        s0 += f.x; s1 += f.y; s2 += f.z; s3 += f.w;
        ((__half2*)xo)[e*2]     = __floats2half2_rn(f.x, f.y);
        ((__half2*)xo)[e*2 + 1] = __floats2half2_rn(f.z, f.w);
    }
    s0 += __shfl_xor_sync(0xffffffffu, s0, 16);
    s1 += __shfl_xor_sync(0xffffffffu, s1, 16);
    s2 += __shfl_xor_sync(0xffffffffu, s2, 16);
    s3 += __shfl_xor_sync(0xffffffffu, s3, 16);
    if (lane < 16) {
        red[warp][v0]   = s0;
        red[warp][v0+1] = s1;
        red[warp][v0+2] = s2;
        red[warp][v0+3] = s3;
    }
    __syncthreads();
    if (tid < 64) {
        float s = 0.f;
        #pragma unroll
        for (int w = 0; w < 8; w++) s += red[w][tid];
        g_tp[bc*Vq + tid] = s * (1.f/Tq);
    }
}

// x1/x2 = conv1x1(tp) — tiled
__global__ void __launch_bounds__(256) k_x1x2(const float* __restrict__ w1, const float* __restrict__ b1,
                                              const float* __restrict__ w2, const float* __restrict__ b2) {
    __shared__ float tps[64][64];
    __shared__ float w1s[16][64];
    __shared__ float w2s[16][64];
    int b = blockIdx.y, ot = blockIdx.x * 16;
    int tid = threadIdx.x;
    int v = tid & 63, og = tid >> 6;
    float a1[4] = {0.f,0.f,0.f,0.f}, a2[4] = {0.f,0.f,0.f,0.f};

    for (int c0 = 0; c0 < Cq; c0 += 64) {
        __syncthreads();
        #pragma unroll
        for (int i = 0; i < 16; i++) {
            int idx = tid + i*256;
            tps[idx >> 6][idx & 63] = g_tp[(b*Cq + c0 + (idx >> 6))*Vq + (idx & 63)];
        }
        #pragma unroll
        for (int i = 0; i < 4; i++) {
            int idx = tid + i*256;
            int o = idx >> 6, cc = idx & 63;
            w1s[o][cc] = w1[(ot + o)*Cq + c0 + cc];
            w2s[o][cc] = w2[(ot + o)*Cq + c0 + cc];
        }
        __syncthreads();
        #pragma unroll 8
        for (int cc = 0; cc < 64; cc++) {
            float t = tps[cc][v];
            #pragma unroll
            for (int j = 0; j < 4; j++) {
                a1[j] = fmaf(t, w1s[og*4 + j][cc], a1[j]);
                a2[j] = fmaf(t, w2s[og*4 + j][cc], a2[j]);
            }
        }
    }
    #pragma unroll
    for (int j = 0; j < 4; j++) {
        int o = ot + og*4 + j;
        g_x1[(b*Oq + o)*Vq + v] = a1[j] + b1[o];
        g_x2[(b*Oq + o)*Vq + v] = a2[j] + b2[o];
    }
}

__global__ void k_adj(const float* __restrict__ Ap, const float* __restrict__ beta_p) {
    __shared__ float x1s[32][Vq];
    __shared__ float x2s[32][Vq];
    __shared__ float S[Vq][Vq];
    int bk = blockIdx.x;
    int b = bk >> 3, k = bk & 7;
    int tid = threadIdx.x;

    for (int i = tid; i < 32*Vq; i += 256) {
        int c = i >> 6, v = i & 63;
        int row = (b*Oq + k*32 + c)*Vq + v;
        x1s[c][v] = g_x1[row];
        x2s[c][v] = g_x2[row];
    }
    __syncthreads();
    for (int i = tid; i < Vq*Vq; i += 256) {
        int v = i >> 6, w = i & 63;
        float s = 0.f;
        #pragma unroll
        for (int c = 0; c < 32; c++) s = fmaf(x1s[c][v], x2s[c][w], s);
        S[v][w] = s;
    }
    __syncthreads();
    if (tid < Vq) {
        int w = tid;
        float m = -1e30f;
        for (int v = 0; v < Vq; v++) m = fmaxf(m, S[v][w]);
        float sum = 0.f;
        for (int v = 0; v < Vq; v++) { float e = __expf(S[v][w] - m); S[v][w] = e; sum += e; }
        float scl = beta_p[0] / sum;
        for (int v = 0; v < Vq; v++)
            g_M[((bk*Vq + v) << 6) + w] = Ap[((k*Vq + v) << 6) + w] + S[v][w]*scl;
    }
}

// ---------------- fp16 GEMM: Y = W(256m) @ X(128n), k=256; deterministic BN partials ----------------
#define WSPh 40
#define XSPh 136
#define WSTh (256*WSPh)           // 10240 halfs
#define XSTh (32*XSPh)            // 4352 halfs
#define GSTAGEh (WSTh + XSTh)     // 14592 halfs = 29184 B
#define NSTAGE 3

__global__ void __launch_bounds__(256, 1) k_gemm(const __half* __restrict__ Wh,
                                                 const __half* __restrict__ Xg,
                                                 int part) {
    extern __shared__ __align__(16) char smraw[];
    __half* smem = (__half*)smraw;
    __shared__ float sred[2][256][2];     // [stat][row][wn]
    int b  = blockIdx.z;
    int n0 = blockIdx.x * 128;
    int tid  = threadIdx.x;
    int warp = tid >> 5, lane = tid & 31;
    int wm = warp >> 1, wn = warp & 1;           // 4 x 2 warps, warp tile 64m x 64n
    int r  = lane >> 2, c = lane & 3;
    int l16 = lane & 15, lh = lane >> 4;

    const __half* Xb = Xg + (size_t)b*Cq*TVq;
    uint32_t sbase = (uint32_t)__cvta_generic_to_shared(smem);

    float acc[4][8][4];
    #pragma unroll
    for (int i = 0; i < 4; i++)
        #pragma unroll
        for (int j = 0; j < 8; j++)
            #pragma unroll
            for (int q = 0; q < 4; q++) acc[i][j][q] = 0.f;

    auto load_stage = [&](int kt, int s) {
        int k0 = kt * 32;
        uint32_t ws = sbase + (uint32_t)s*GSTAGEh*2;
        uint32_t xs = ws + WSTh*2;
        #pragma unroll
        for (int i = 0; i < 4; i++) {                  // W: 256 x 32
            int idx = tid + i*256;
            int m = idx >> 2, ch = idx & 3;
            cpasync16(ws + (m*WSPh + ch*8)*2, &Wh[(size_t)m*Cq + k0 + ch*8]);
        }
        #pragma unroll
        for (int i = 0; i < 2; i++) {                  // X: 32 x 128
            int idx = tid + i*256;
            int k = idx >> 4, ch = idx & 15;
            cpasync16(xs + (k*XSPh + ch*8)*2, &Xb[(size_t)(k0 + k)*TVq + n0 + ch*8]);
        }
        CP_COMMIT();
    };

    load_stage(0, 0);
    load_stage(1, 1);

    #pragma unroll
    for (int kt = 0; kt < 8; kt++) {
        // DRAIN FIX: on the last iteration the group filling this stage is the
        // most-recently-committed one; wait_group 1 would legally leave it in
        // flight while we read the tile. Wait for ALL groups at kt == 7.
        if (kt == 7) { CP_WAIT(0); } else { CP_WAIT(1); }
        __syncthreads();
        if (kt + 2 < 8) load_stage(kt + 2, (kt + 2) % NSTAGE);

        uint32_t ws = sbase + (uint32_t)(kt % NSTAGE)*GSTAGEh*2;
        uint32_t xs = ws + WSTh*2;

        #pragma unroll
        for (int ks = 0; ks < 2; ks++) {
            uint32_t Af[4][4];
            #pragma unroll
            for (int mi = 0; mi < 4; mi++)
                ldsm_x4(Af[mi][0], Af[mi][1], Af[mi][2], Af[mi][3],
                        ws + ((wm*64 + mi*16 + l16)*WSPh + ks*16 + 8*lh)*2);
            uint32_t Bf[4][4];
            #pragma unroll
            for (int p = 0; p < 4; p++)
                ldsm_x4_t(Bf[p][0], Bf[p][1], Bf[p][2], Bf[p][3],
                          xs + ((ks*16 + l16)*XSPh + wn*64 + p*16 + 8*lh)*2);
            #pragma unroll
            for (int mi = 0; mi < 4; mi++)
                #pragma unroll
                for (int p = 0; p < 4; p++) {
                    mma_f16(acc[mi][2*p],   Af[mi][0], Af[mi][1], Af[mi][2], Af[mi][3],
                            Bf[p][0], Bf[p][1]);
                    mma_f16(acc[mi][2*p+1], Af[mi][0], Af[mi][1], Af[mi][2], Af[mi][3],
                            Bf[p][2], Bf[p][3]);
                }
        }
        __syncthreads();
    }

    // epilogue: fp16 store + deterministic BN partials
    __half* Yb = g_bufAh + (size_t)b*Oq*TVq;
    #pragma unroll
    for (int mi = 0; mi < 4; mi++) {
        #pragma unroll
        for (int h = 0; h < 2; h++) {
            int row = wm*64 + mi*16 + h*8 + r;
            float s = 0.f, q = 0.f;
            #pragma unroll
            for (int ni = 0; ni < 8; ni++) {
                float v0 = acc[mi][ni][2*h], v1 = acc[mi][ni][2*h + 1];
                s += v0 + v1;
                q  = fmaf(v0, v0, fmaf(v1, v1, q));
                int col = n0 + wn*64 + ni*8 + 2*c;
                *(__half2*)&Yb[(size_t)row*TVq + col] = __floats2half2_rn(v0, v1);
            }
            s += __shfl_xor_sync(0xffffffffu, s, 1);
            s += __shfl_xor_sync(0xffffffffu, s, 2);
            q += __shfl_xor_sync(0xffffffffu, q, 1);
            q += __shfl_xor_sync(0xffffffffu, q, 2);
            if (c == 0) {
                sred[0][row][wn] = s;
                sred[1][row][wn] = q;
            }
        }
    }
    __syncthreads();
    int blk = blockIdx.z*64 + blockIdx.x;          // 0..1023
    g_psum[part][blk][tid] = sred[0][tid][0] + sred[0][tid][1];
    g_psq [part][blk][tid] = sred[1][tid][0] + sred[1][tid][1];
}

// deterministic reduction of BN partials -> g_stats
__global__ void k_redstats(int part) {
    int o = blockIdx.x, tid = threadIdx.x;
    float s = 0.f, q = 0.f;
    #pragma unroll
    for (int i = 0; i < 4; i++) {
        s += g_psum[part][tid + i*256][o];
        q += g_psq [part][tid + i*256][o];
    }
    __shared__ float ss[256], qq[256];
    ss[tid] = s; qq[tid] = q;
    __syncthreads();
    for (int st = 128; st > 0; st >>= 1) {
        if (tid < st) { ss[tid] += ss[tid + st]; qq[tid] += qq[tid + st]; }
        __syncthreads();
    }
    if (tid == 0) {
        g_stats[part*2*Oq + o]      = ss[0];
        g_stats[part*2*Oq + Oq + o] = qq[0];
    }
}

// ---------------- stage5 ----------------
#define HSPh 72
#define ASPh 72
#define S5H (128*HSPh + 64*ASPh)

__global__ void __launch_bounds__(256) k_stage5(const float* __restrict__ alpha_p,
                                                const float* __restrict__ gamma,
                                                const float* __restrict__ beta) {
    extern __shared__ __align__(16) char smraw[];
    __half* hs = (__half*)smraw;
    __half* As = hs + 128*HSPh;

    int bx = blockIdx.x;
    int b = bx >> 8, o = bx & 255, k = o >> 5;
    int tid  = threadIdx.x;
    int warp = tid >> 5, lane = tid & 31;
    int wm = warp >> 1, wn = warp & 1;
    int r  = lane >> 2, c = lane & 3;
    int l16 = lane & 15, lh = lane >> 4;

    float mean  = g_stats[o]      * (1.f/CNT);
    float var   = g_stats[Oq + o] * (1.f/CNT) - mean*mean;
    float scale = gamma[o] * rsqrtf(var + 1e-5f);
    float shift = beta[o] - mean*scale;

    const __half* src = g_bufAh + (size_t)bx*TVq;
    for (int i = tid; i < TVq/8; i += 256) {
        int t = (i*8) >> 6, v = (i*8) & 63;
        const __half2* s2 = (const __half2*)(src + i*8);
        __half2 out[4];
        #pragma unroll
        for (int j = 0; j < 4; j++) {
            float2 f = __half22float2(s2[j]);
            out[j] = __floats2half2_rn(fmaxf(fmaf(f.x, scale, shift), 0.f),
                                       fmaxf(fmaf(f.y, scale, shift), 0.f));
        }
        *(uint2*)&hs[t*HSPh + v]     = *(uint2*)&out[0];
        *(uint2*)&hs[t*HSPh + v + 4] = *(uint2*)&out[2];
    }

    float alpha = alpha_p[0];
    const float* x1r = g_x1 + bx*Vq;
    const float* x2r = g_x2 + bx*Vq;
    const float* Mp  = g_M + (size_t)(b*Kq + k)*Vq*Vq;
    for (int i = tid; i < Vq*Vq; i += 256) {
        int v = i >> 6, w = i & 63;
        As[v*ASPh + w] = __float2half(Mp[i] + alpha * tanhf(x1r[v] - x2r[w]));
    }
    __syncthreads();

    uint32_t hsb = (uint32_t)__cvta_generic_to_shared(hs);
    uint32_t asb = (uint32_t)__cvta_generic_to_shared(As);

    float acc[2][4][4];
    #pragma unroll
    for (int i = 0; i < 2; i++)
        #pragma unroll
        for (int j = 0; j < 4; j++)
            #pragma unroll
            for (int q = 0; q < 4; q++) acc[i][j][q] = 0.f;

    #pragma unroll
    for (int ks = 0; ks < 4; ks++) {
        uint32_t Af[2][4];
        #pragma unroll
        for (int mi = 0; mi < 2; mi++)
            ldsm_x4(Af[mi][0], Af[mi][1], Af[mi][2], Af[mi][3],
                    hsb + ((wm*32 + mi*16 + l16)*HSPh + ks*16 + 8*lh)*2);
        uint32_t Bf[2][4];
        #pragma unroll
        for (int p = 0; p < 2; p++)
            ldsm_x4_t(Bf[p][0], Bf[p][1], Bf[p][2], Bf[p][3],
                      asb + ((ks*16 + l16)*ASPh + wn*32 + p*16 + 8*lh)*2);
        #pragma unroll
        for (int mi = 0; mi < 2; mi++)
            #pragma unroll
            for (int p = 0; p < 2; p++) {
                mma_f16(acc[mi][2*p],   Af[mi][0], Af[mi][1], Af[mi][2], Af[mi][3],
                        Bf[p][0], Bf[p][1]);
                mma_f16(acc[mi][2*p+1], Af[mi][0], Af[mi][1], Af[mi][2], Af[mi][3],
                        Bf[p][2], Bf[p][3]);
            }
    }

    __half* dst = g_bufBh + (size_t)bx*TVq;
    #pragma unroll
    for (int mi = 0; mi < 2; mi++) {
        int row = wm*32 + mi*16 + r;
        #pragma unroll
        for (int ni = 0; ni < 4; ni++) {
            int col = wn*32 + ni*8 + 2*c;
            *(__half2*)&dst[row*Vq + col]       = __floats2half2_rn(acc[mi][ni][0], acc[mi][ni][1]);
            *(__half2*)&dst[(row + 8)*Vq + col] = __floats2half2_rn(acc[mi][ni][2], acc[mi][ni][3]);
        }
    }
}

// out = relu(BN(z) + x),  z fp16
__global__ void k_out(const float* __restrict__ x,
                      const float* __restrict__ gamma, const float* __restrict__ beta,
                      float* __restrict__ out) {
    size_t i4 = (size_t)blockIdx.x * 256 + threadIdx.x;
    int o = (int)((i4 >> 11) & 255);
    float mean  = g_stats[2*Oq + o] * (1.f/CNT);
    float var   = g_stats[3*Oq + o] * (1.f/CNT) - mean*mean;
    float scale = gamma[o] * rsqrtf(var + 1e-5f);
    float shift = beta[o] - mean*scale;
    const __half2* zp = (const __half2*)(g_bufAh) + i4*2;
    float2 z0 = __half22float2(zp[0]);
    float2 z1 = __half22float2(zp[1]);
    float4 xv = ((const float4*)x)[i4];
    float4 rr;
    rr.x = fmaxf(fmaf(z0.x, scale, shift) + xv.x, 0.f);
    rr.y = fmaxf(fmaf(z0.y, scale, shift) + xv.y, 0.f);
    rr.z = fmaxf(fmaf(z1.x, scale, shift) + xv.z, 0.f);
    rr.w = fmaxf(fmaf(z1.y, scale, shift) + xv.w, 0.f);
    ((float4*)out)[i4] = rr;
}

// ---------------- launch ----------------
extern "C" void kernel_launch(void* const* d_in, const int* in_sizes, int n_in,
                              void* d_out, int out_size) {
    const float* x       = (const float*)d_in[0];
    const float* A_param = (const float*)d_in[1];
    const float* alpha   = (const float*)d_in[2];
    const float* beta    = (const float*)d_in[3];
    const float* w1      = (const float*)d_in[4];
    const float* b1      = (const float*)d_in[5];
    const float* w2      = (const float*)d_in[6];
    const float* b2      = (const float*)d_in[7];
    const float* stem_w  = (const float*)d_in[8];
    const float* stem_g  = (const float*)d_in[10];
    const float* stem_be = (const float*)d_in[11];
    const float* head_w  = (const float*)d_in[12];
    const float* head_g  = (const float*)d_in[14];
    const float* head_be = (const float*)d_in[15];
    float* out = (float*)d_out;

    int gemm_smem   = NSTAGE * GSTAGEh * 2;   // 87552 B
    int stage5_smem = S5H * 2;                // 27648 B
    cudaFuncSetAttribute(k_gemm,   cudaFuncAttributeMaxDynamicSharedMemorySize, gemm_smem);
    cudaFuncSetAttribute(k_stage5, cudaFuncAttributeMaxDynamicSharedMemorySize, stage5_smem);

    __half* whp = nullptr;  cudaGetSymbolAddress((void**)&whp, g_wh);
    __half* xhp = nullptr;  cudaGetSymbolAddress((void**)&xhp, g_xh);
    __half* bBp = nullptr;  cudaGetSymbolAddress((void**)&bBp, g_bufBh);

    k_init<<<Oq*Cq/256, 256>>>(stem_w, head_w);
    k_meanT<<<Bq*Cq, 256>>>(x);
    k_x1x2<<<dim3(Oq/16, Bq), 256>>>(w1, b1, w2, b2);
    k_adj<<<Bq*Kq, 256>>>(A_param, beta);

    // stem conv + deterministic BN partials (bias cancels in BN)
    k_gemm<<<dim3(TVq/128, 1, Bq), 256, gemm_smem>>>(whp, xhp, 0);
    k_redstats<<<Oq, 256>>>(0);

    // BN+relu + graph matmul
    k_stage5<<<Bq*Oq, 256, stage5_smem>>>(alpha, stem_g, stem_be);

    // head conv + deterministic BN partials
    k_gemm<<<dim3(TVq/128, 1, Bq), 256, gemm_smem>>>(whp + Oq*Cq, bBp, 1);
    k_redstats<<<Oq, 256>>>(1);

    k_out<<<(int)(((size_t)Bq*Oq*TVq/4)/256), 256>>>(x, head_g, head_be, out);
}

// round 8
// speedup vs baseline: 3.7030x; 1.0279x over previous
#include <cuda_runtime.h>
#include <cuda_fp16.h>
#include <cmath>
#include <cstdint>

#define Bq 16
#define Cq 256
#define Tq 128
#define Vq 64
#define Kq 8
#define Oq 256
#define TVq 8192
#define CNT 131072
#define NBLK 1024            // GEMM blocks per launch = 64 * 16

// ---------------- scratch ----------------
__device__ float  g_tp[Bq*Cq*Vq];
__device__ float  g_x1[Bq*Oq*Vq];
__device__ float  g_x2[Bq*Oq*Vq];
__device__ float  g_M [Bq*Kq*Vq*Vq];
__device__ float  g_stats[4*Oq];
__device__ float  g_psum[2][NBLK][Oq];         // deterministic BN partials
__device__ float  g_psq [2][NBLK][Oq];
__device__ __half g_xh  [(size_t)Bq*Cq*TVq];   // fp16 copy of x
__device__ __half g_bufAh[(size_t)Bq*Oq*TVq];  // stem out y / head out z (fp16)
__device__ __half g_bufBh[(size_t)Bq*Oq*TVq];  // stage5 out (fp16)
__device__ __half g_wh[2*Oq*Cq];               // fp16 stem_w, head_w

// ---------------- helpers ----------------
__device__ __forceinline__ void mma_f16(float c[4],
                                        uint32_t a0, uint32_t a1, uint32_t a2, uint32_t a3,
                                        uint32_t b0, uint32_t b1) {
    asm volatile(
        "mma.sync.aligned.m16n8k16.row.col.f32.f16.f16.f32 "
        "{%0,%1,%2,%3},{%4,%5,%6,%7},{%8,%9},{%0,%1,%2,%3};\n"
        : "+f"(c[0]), "+f"(c[1]), "+f"(c[2]), "+f"(c[3])
        : "r"(a0), "r"(a1), "r"(a2), "r"(a3), "r"(b0), "r"(b1));
}
__device__ __forceinline__ void ldsm_x4(uint32_t& r0, uint32_t& r1, uint32_t& r2, uint32_t& r3,
                                        uint32_t addr) {
    asm volatile("ldmatrix.sync.aligned.m8n8.x4.shared.b16 {%0,%1,%2,%3}, [%4];\n"
                 : "=r"(r0), "=r"(r1), "=r"(r2), "=r"(r3) : "r"(addr));
}
__device__ __forceinline__ void ldsm_x4_t(uint32_t& r0, uint32_t& r1, uint32_t& r2, uint32_t& r3,
                                          uint32_t addr) {
    asm volatile("ldmatrix.sync.aligned.m8n8.x4.trans.shared.b16 {%0,%1,%2,%3}, [%4];\n"
                 : "=r"(r0), "=r"(r1), "=r"(r2), "=r"(r3) : "r"(addr));
}
__device__ __forceinline__ void cpasync16(uint32_t saddr, const void* g) {
    asm volatile("cp.async.cg.shared.global [%0], [%1], 16;\n" :: "r"(saddr), "l"(g));
}
#define CP_COMMIT() asm volatile("cp.async.commit_group;\n" ::: "memory")
#define CP_WAIT(n)  asm volatile("cp.async.wait_group %0;\n" :: "n"(n) : "memory")

// ---------------- init: fp16 weights only ----------------
__global__ void k_init(const float* __restrict__ w1, const float* __restrict__ w2) {
    int i = blockIdx.x*256 + threadIdx.x;           // 65536 total
    g_wh[i]         = __float2half(w1[i]);
    g_wh[Oq*Cq + i] = __float2half(w2[i]);
}

// x -> fp16 copy + per-(b,c) mean over T (shfl reduce, deterministic)
__global__ void k_meanT(const float* __restrict__ x) {
    int bc = blockIdx.x;
    int tid = threadIdx.x;
    int lane = tid & 31, warp = tid >> 5;
    __shared__ float red[8][64];
    const float4* p = (const float4*)(x + (size_t)bc*TVq);
    __half* xo = g_xh + (size_t)bc*TVq;
    float s0=0.f, s1=0.f, s2=0.f, s3=0.f;
    int v0 = (tid*4) & 63;
    #pragma unroll
    for (int i = 0; i < 8; i++) {
        int e = tid + i*256;
        float4 f = p[e];
        s0 += f.x; s1 += f.y; s2 += f.z; s3 += f.w;
        ((__half2*)xo)[e*2]     = __floats2half2_rn(f.x, f.y);
        ((__half2*)xo)[e*2 + 1] = __floats2half2_rn(f.z, f.w);
    }
    s0 += __shfl_xor_sync(0xffffffffu, s0, 16);
    s1 += __shfl_xor_sync(0xffffffffu, s1, 16);
    s2 += __shfl_xor_sync(0xffffffffu, s2, 16);
    s3 += __shfl_xor_sync(0xffffffffu, s3, 16);
    if (lane < 16) {
        red[warp][v0]   = s0;
        red[warp][v0+1] = s1;
        red[warp][v0+2] = s2;
        red[warp][v0+3] = s3;
    }
    __syncthreads();
    if (tid < 64) {
        float s = 0.f;
        #pragma unroll
        for (int w = 0; w < 8; w++) s += red[w][tid];
        g_tp[bc*Vq + tid] = s * (1.f/Tq);
    }
}

// x1/x2 = conv1x1(tp) — tiled
__global__ void __launch_bounds__(256) k_x1x2(const float* __restrict__ w1, const float* __restrict__ b1,
                                              const float* __restrict__ w2, const float* __restrict__ b2) {
    __shared__ float tps[64][64];
    __shared__ float w1s[16][64];
    __shared__ float w2s[16][64];
    int b = blockIdx.y, ot = blockIdx.x * 16;
    int tid = threadIdx.x;
    int v = tid & 63, og = tid >> 6;
    float a1[4] = {0.f,0.f,0.f,0.f}, a2[4] = {0.f,0.f,0.f,0.f};

    for (int c0 = 0; c0 < Cq; c0 += 64) {
        __syncthreads();
        #pragma unroll
        for (int i = 0; i < 16; i++) {
            int idx = tid + i*256;
            tps[idx >> 6][idx & 63] = g_tp[(b*Cq + c0 + (idx >> 6))*Vq + (idx & 63)];
        }
        #pragma unroll
        for (int i = 0; i < 4; i++) {
            int idx = tid + i*256;
            int o = idx >> 6, cc = idx & 63;
            w1s[o][cc] = w1[(ot + o)*Cq + c0 + cc];
            w2s[o][cc] = w2[(ot + o)*Cq + c0 + cc];
        }
        __syncthreads();
        #pragma unroll 8
        for (int cc = 0; cc < 64; cc++) {
            float t = tps[cc][v];
            #pragma unroll
            for (int j = 0; j < 4; j++) {
                a1[j] = fmaf(t, w1s[og*4 + j][cc], a1[j]);
                a2[j] = fmaf(t, w2s[og*4 + j][cc], a2[j]);
            }
        }
    }
    #pragma unroll
    for (int j = 0; j < 4; j++) {
        int o = ot + og*4 + j;
        g_x1[(b*Oq + o)*Vq + v] = a1[j] + b1[o];
        g_x2[(b*Oq + o)*Vq + v] = a2[j] + b2[o];
    }
}

// M = A_param + beta * softmax; softmax parallelized over 256 threads
__global__ void k_adj(const float* __restrict__ Ap, const float* __restrict__ beta_p) {
    __shared__ float x1s[32][Vq];
    __shared__ float x2s[32][Vq];
    __shared__ float S[Vq][Vq];
    __shared__ float mred[4][64];
    __shared__ float sred2[4][64];
    int bk = blockIdx.x;
    int b = bk >> 3, k = bk & 7;
    int tid = threadIdx.x;

    for (int i = tid; i < 32*Vq; i += 256) {
        int c = i >> 6, v = i & 63;
        int row = (b*Oq + k*32 + c)*Vq + v;
        x1s[c][v] = g_x1[row];
        x2s[c][v] = g_x2[row];
    }
    __syncthreads();
    for (int i = tid; i < Vq*Vq; i += 256) {
        int v = i >> 6, w = i & 63;
        float s = 0.f;
        #pragma unroll
        for (int c = 0; c < 32; c++) s = fmaf(x1s[c][v], x2s[c][w], s);
        S[v][w] = s;
    }
    __syncthreads();

    // softmax over v (per column w): 4 threads per w handle 16 v's each
    int w = tid & 63, part = tid >> 6;
    int vlo = part*16;
    float m = -1e30f;
    #pragma unroll
    for (int v = 0; v < 16; v++) m = fmaxf(m, S[vlo + v][w]);
    mred[part][w] = m;
    __syncthreads();
    m = fmaxf(fmaxf(mred[0][w], mred[1][w]), fmaxf(mred[2][w], mred[3][w]));
    float sum = 0.f;
    #pragma unroll
    for (int v = 0; v < 16; v++) {
        float e = __expf(S[vlo + v][w] - m);
        S[vlo + v][w] = e;
        sum += e;
    }
    sred2[part][w] = sum;
    __syncthreads();
    float tot = sred2[0][w] + sred2[1][w] + sred2[2][w] + sred2[3][w];
    float scl = beta_p[0] / tot;
    #pragma unroll
    for (int v = 0; v < 16; v++) {
        int vv = vlo + v;
        g_M[((bk*Vq + vv) << 6) + w] = Ap[((k*Vq + vv) << 6) + w] + S[vv][w]*scl;
    }
}

// ---------------- fp16 GEMM: Y = W(256m) @ X(128n), k=256; 4-stage; BN partials ----------------
#define WSPh 40
#define XSPh 136
#define WSTh (256*WSPh)           // 10240 halfs
#define XSTh (32*XSPh)            // 4352 halfs
#define GSTAGEh (WSTh + XSTh)     // 14592 halfs = 29184 B
#define NSTAGE 4

__global__ void __launch_bounds__(256, 1) k_gemm(const __half* __restrict__ Wh,
                                                 const __half* __restrict__ Xg,
                                                 int part) {
    extern __shared__ __align__(16) char smraw[];
    __half* smem = (__half*)smraw;
    __shared__ float sred[2][256][2];     // [stat][row][wn]
    int b  = blockIdx.z;
    int n0 = blockIdx.x * 128;
    int tid  = threadIdx.x;
    int warp = tid >> 5, lane = tid & 31;
    int wm = warp >> 1, wn = warp & 1;           // 4 x 2 warps, warp tile 64m x 64n
    int r  = lane >> 2, c = lane & 3;
    int l16 = lane & 15, lh = lane >> 4;

    const __half* Xb = Xg + (size_t)b*Cq*TVq;
    uint32_t sbase = (uint32_t)__cvta_generic_to_shared(smem);

    float acc[4][8][4];
    #pragma unroll
    for (int i = 0; i < 4; i++)
        #pragma unroll
        for (int j = 0; j < 8; j++)
            #pragma unroll
            for (int q = 0; q < 4; q++) acc[i][j][q] = 0.f;

    auto load_stage = [&](int kt, int s) {
        int k0 = kt * 32;
        uint32_t ws = sbase + (uint32_t)s*GSTAGEh*2;
        uint32_t xs = ws + WSTh*2;
        #pragma unroll
        for (int i = 0; i < 4; i++) {                  // W: 256 x 32
            int idx = tid + i*256;
            int m = idx >> 2, ch = idx & 3;
            cpasync16(ws + (m*WSPh + ch*8)*2, &Wh[(size_t)m*Cq + k0 + ch*8]);
        }
        #pragma unroll
        for (int i = 0; i < 2; i++) {                  // X: 32 x 128
            int idx = tid + i*256;
            int k = idx >> 4, ch = idx & 15;
            cpasync16(xs + (k*XSPh + ch*8)*2, &Xb[(size_t)(k0 + k)*TVq + n0 + ch*8]);
        }
        CP_COMMIT();
    };

    load_stage(0, 0);
    load_stage(1, 1);
    load_stage(2, 2);

    #pragma unroll
    for (int kt = 0; kt < 8; kt++) {
        // exact drain: group kt must be complete before reading its stage.
        // in-flight before wait: {kt..min(kt+2,7)} -> wait counts 2,2,2,2,2,2,1,0
        if (kt == 7)      { CP_WAIT(0); }
        else if (kt == 6) { CP_WAIT(1); }
        else              { CP_WAIT(2); }
        __syncthreads();
        if (kt + 3 < 8) load_stage(kt + 3, (kt + 3) % NSTAGE);

        uint32_t ws = sbase + (uint32_t)(kt % NSTAGE)*GSTAGEh*2;
        uint32_t xs = ws + WSTh*2;

        #pragma unroll
        for (int ks = 0; ks < 2; ks++) {
            uint32_t Af[4][4];
            #pragma unroll
            for (int mi = 0; mi < 4; mi++)
                ldsm_x4(Af[mi][0], Af[mi][1], Af[mi][2], Af[mi][3],
                        ws + ((wm*64 + mi*16 + l16)*WSPh + ks*16 + 8*lh)*2);
            uint32_t Bf[4][4];
            #pragma unroll
            for (int p = 0; p < 4; p++)
                ldsm_x4_t(Bf[p][0], Bf[p][1], Bf[p][2], Bf[p][3],
                          xs + ((ks*16 + l16)*XSPh + wn*64 + p*16 + 8*lh)*2);
            #pragma unroll
            for (int mi = 0; mi < 4; mi++)
                #pragma unroll
                for (int p = 0; p < 4; p++) {
                    mma_f16(acc[mi][2*p],   Af[mi][0], Af[mi][1], Af[mi][2], Af[mi][3],
                            Bf[p][0], Bf[p][1]);
                    mma_f16(acc[mi][2*p+1], Af[mi][0], Af[mi][1], Af[mi][2], Af[mi][3],
                            Bf[p][2], Bf[p][3]);
                }
        }
        __syncthreads();
    }

    // epilogue: fp16 store + deterministic BN partials
    __half* Yb = g_bufAh + (size_t)b*Oq*TVq;
    #pragma unroll
    for (int mi = 0; mi < 4; mi++) {
        #pragma unroll
        for (int h = 0; h < 2; h++) {
            int row = wm*64 + mi*16 + h*8 + r;
            float s = 0.f, q = 0.f;
            #pragma unroll
            for (int ni = 0; ni < 8; ni++) {
                float v0 = acc[mi][ni][2*h], v1 = acc[mi][ni][2*h + 1];
                s += v0 + v1;
                q  = fmaf(v0, v0, fmaf(v1, v1, q));
                int col = n0 + wn*64 + ni*8 + 2*c;
                *(__half2*)&Yb[(size_t)row*TVq + col] = __floats2half2_rn(v0, v1);
            }
            s += __shfl_xor_sync(0xffffffffu, s, 1);
            s += __shfl_xor_sync(0xffffffffu, s, 2);
            q += __shfl_xor_sync(0xffffffffu, q, 1);
            q += __shfl_xor_sync(0xffffffffu, q, 2);
            if (c == 0) {
                sred[0][row][wn] = s;
                sred[1][row][wn] = q;
            }
        }
    }
    __syncthreads();
    int blk = blockIdx.z*64 + blockIdx.x;          // 0..1023
    g_psum[part][blk][tid] = sred[0][tid][0] + sred[0][tid][1];
    g_psq [part][blk][tid] = sred[1][tid][0] + sred[1][tid][1];
}

// deterministic reduction of BN partials -> g_stats
__global__ void k_redstats(int part) {
    int o = blockIdx.x, tid = threadIdx.x;
    float s = 0.f, q = 0.f;
    #pragma unroll
    for (int i = 0; i < 4; i++) {
        s += g_psum[part][tid + i*256][o];
        q += g_psq [part][tid + i*256][o];
    }
    __shared__ float ss[256], qq[256];
    ss[tid] = s; qq[tid] = q;
    __syncthreads();
    for (int st = 128; st > 0; st >>= 1) {
        if (tid < st) { ss[tid] += ss[tid + st]; qq[tid] += qq[tid + st]; }
        __syncthreads();
    }
    if (tid == 0) {
        g_stats[part*2*Oq + o]      = ss[0];
        g_stats[part*2*Oq + Oq + o] = qq[0];
    }
}

// ---------------- stage5 ----------------
#define HSPh 72
#define ASPh 72
#define S5H (128*HSPh + 64*ASPh)

__global__ void __launch_bounds__(256) k_stage5(const float* __restrict__ alpha_p,
                                                const float* __restrict__ gamma,
                                                const float* __restrict__ beta) {
    extern __shared__ __align__(16) char smraw[];
    __half* hs = (__half*)smraw;
    __half* As = hs + 128*HSPh;

    int bx = blockIdx.x;
    int b = bx >> 8, o = bx & 255, k = o >> 5;
    int tid  = threadIdx.x;
    int warp = tid >> 5, lane = tid & 31;
    int wm = warp >> 1, wn = warp & 1;
    int r  = lane >> 2, c = lane & 3;
    int l16 = lane & 15, lh = lane >> 4;

    float mean  = g_stats[o]      * (1.f/CNT);
    float var   = g_stats[Oq + o] * (1.f/CNT) - mean*mean;
    float scale = gamma[o] * rsqrtf(var + 1e-5f);
    float shift = beta[o] - mean*scale;

    const __half* src = g_bufAh + (size_t)bx*TVq;
    for (int i = tid; i < TVq/8; i += 256) {
        int t = (i*8) >> 6, v = (i*8) & 63;
        const __half2* s2 = (const __half2*)(src + i*8);
        __half2 out[4];
        #pragma unroll
        for (int j = 0; j < 4; j++) {
            float2 f = __half22float2(s2[j]);
            out[j] = __floats2half2_rn(fmaxf(fmaf(f.x, scale, shift), 0.f),
                                       fmaxf(fmaf(f.y, scale, shift), 0.f));
        }
        *(uint2*)&hs[t*HSPh + v]     = *(uint2*)&out[0];
        *(uint2*)&hs[t*HSPh + v + 4] = *(uint2*)&out[2];
    }

    float alpha = alpha_p[0];
    const float* x1r = g_x1 + bx*Vq;
    const float* x2r = g_x2 + bx*Vq;
    const float* Mp  = g_M + (size_t)(b*Kq + k)*Vq*Vq;
    for (int i = tid; i < Vq*Vq; i += 256) {
        int v = i >> 6, w = i & 63;
        As[v*ASPh + w] = __float2half(Mp[i] + alpha * tanhf(x1r[v] - x2r[w]));
    }
    __syncthreads();

    uint32_t hsb = (uint32_t)__cvta_generic_to_shared(hs);
    uint32_t asb = (uint32_t)__cvta_generic_to_shared(As);

    float acc[2][4][4];
    #pragma unroll
    for (int i = 0; i < 2; i++)
        #pragma unroll
        for (int j = 0; j < 4; j++)
            #pragma unroll
            for (int q = 0; q < 4; q++) acc[i][j][q] = 0.f;

    #pragma unroll
    for (int ks = 0; ks < 4; ks++) {
        uint32_t Af[2][4];
        #pragma unroll
        for (int mi = 0; mi < 2; mi++)
            ldsm_x4(Af[mi][0], Af[mi][1], Af[mi][2], Af[mi][3],
                    hsb + ((wm*32 + mi*16 + l16)*HSPh + ks*16 + 8*lh)*2);
        uint32_t Bf[2][4];
        #pragma unroll
        for (int p = 0; p < 2; p++)
            ldsm_x4_t(Bf[p][0], Bf[p][1], Bf[p][2], Bf[p][3],
                      asb + ((ks*16 + l16)*ASPh + wn*32 + p*16 + 8*lh)*2);
        #pragma unroll
        for (int mi = 0; mi < 2; mi++)
            #pragma unroll
            for (int p = 0; p < 2; p++) {
                mma_f16(acc[mi][2*p],   Af[mi][0], Af[mi][1], Af[mi][2], Af[mi][3],
                        Bf[p][0], Bf[p][1]);
                mma_f16(acc[mi][2*p+1], Af[mi][0], Af[mi][1], Af[mi][2], Af[mi][3],
                        Bf[p][2], Bf[p][3]);
            }
    }

    __half* dst = g_bufBh + (size_t)bx*TVq;
    #pragma unroll
    for (int mi = 0; mi < 2; mi++) {
        int row = wm*32 + mi*16 + r;
        #pragma unroll
        for (int ni = 0; ni < 4; ni++) {
            int col = wn*32 + ni*8 + 2*c;
            *(__half2*)&dst[row*Vq + col]       = __floats2half2_rn(acc[mi][ni][0], acc[mi][ni][1]);
            *(__half2*)&dst[(row + 8)*Vq + col] = __floats2half2_rn(acc[mi][ni][2], acc[mi][ni][3]);
        }
    }
}

// out = relu(BN(z) + x),  z fp16, residual from fp16 x-copy
__global__ void k_out(const float* __restrict__ gamma, const float* __restrict__ beta,
                      float* __restrict__ out) {
    size_t i4 = (size_t)blockIdx.x * 256 + threadIdx.x;
    int o = (int)((i4 >> 11) & 255);
    float mean  = g_stats[2*Oq + o] * (1.f/CNT);
    float var   = g_stats[3*Oq + o] * (1.f/CNT) - mean*mean;
    float scale = gamma[o] * rsqrtf(var + 1e-5f);
    float shift = beta[o] - mean*scale;
    const __half2* zp = (const __half2*)(g_bufAh) + i4*2;
    const __half2* xp = (const __half2*)(g_xh)    + i4*2;
    float2 z0 = __half22float2(zp[0]);
    float2 z1 = __half22float2(zp[1]);
    float2 x0 = __half22float2(xp[0]);
    float2 x1 = __half22float2(xp[1]);
    float4 rr;
    rr.x = fmaxf(fmaf(z0.x, scale, shift) + x0.x, 0.f);
    rr.y = fmaxf(fmaf(z0.y, scale, shift) + x0.y, 0.f);
    rr.z = fmaxf(fmaf(z1.x, scale, shift) + x1.x, 0.f);
    rr.w = fmaxf(fmaf(z1.y, scale, shift) + x1.y, 0.f);
    ((float4*)out)[i4] = rr;
}

// ---------------- launch ----------------
extern "C" void kernel_launch(void* const* d_in, const int* in_sizes, int n_in,
                              void* d_out, int out_size) {
    const float* x       = (const float*)d_in[0];
    const float* A_param = (const float*)d_in[1];
    const float* alpha   = (const float*)d_in[2];
    const float* beta    = (const float*)d_in[3];
    const float* w1      = (const float*)d_in[4];
    const float* b1      = (const float*)d_in[5];
    const float* w2      = (const float*)d_in[6];
    const float* b2      = (const float*)d_in[7];
    const float* stem_w  = (const float*)d_in[8];
    const float* stem_g  = (const float*)d_in[10];
    const float* stem_be = (const float*)d_in[11];
    const float* head_w  = (const float*)d_in[12];
    const float* head_g  = (const float*)d_in[14];
    const float* head_be = (const float*)d_in[15];
    float* out = (float*)d_out;

    int gemm_smem   = NSTAGE * GSTAGEh * 2;   // 116736 B
    int stage5_smem = S5H * 2;                // 27648 B
    cudaFuncSetAttribute(k_gemm,   cudaFuncAttributeMaxDynamicSharedMemorySize, gemm_smem);
    cudaFuncSetAttribute(k_stage5, cudaFuncAttributeMaxDynamicSharedMemorySize, stage5_smem);

    __half* whp = nullptr;  cudaGetSymbolAddress((void**)&whp, g_wh);
    __half* xhp = nullptr;  cudaGetSymbolAddress((void**)&xhp, g_xh);
    __half* bBp = nullptr;  cudaGetSymbolAddress((void**)&bBp, g_bufBh);

    k_init<<<Oq*Cq/256, 256>>>(stem_w, head_w);
    k_meanT<<<Bq*Cq, 256>>>(x);
    k_x1x2<<<dim3(Oq/16, Bq), 256>>>(w1, b1, w2, b2);
    k_adj<<<Bq*Kq, 256>>>(A_param, beta);

    // stem conv + deterministic BN partials (bias cancels in BN)
    k_gemm<<<dim3(TVq/128, 1, Bq), 256, gemm_smem>>>(whp, xhp, 0);
    k_redstats<<<Oq, 256>>>(0);

    // BN+relu + graph matmul
    k_stage5<<<Bq*Oq, 256, stage5_smem>>>(alpha, stem_g, stem_be);

    // head conv + deterministic BN partials
    k_gemm<<<dim3(TVq/128, 1, Bq), 256, gemm_smem>>>(whp + Oq*Cq, bBp, 1);
    k_redstats<<<Oq, 256>>>(1);

    k_out<<<(int)(((size_t)Bq*Oq*TVq/4)/256), 256>>>(head_g, head_be, out);
}